// round 1
// baseline (speedup 1.0000x reference)
#include <cuda_runtime.h>
#include <math.h>

#define Bsz   32
#define Hdim  56
#define Wdim  56
#define Cc    192
#define WSz   7
#define SHIFT 3
#define NHd   6
#define HD    32
#define NN    49
#define NWIN  64            // (56/7)^2
#define BWIN  (Bsz*NWIN)    // 2048
#define TOK   (BWIN*NN)     // 100352
#define QSCALE 0.17677669529663689f

// ---- scratch (device globals; no allocation allowed) ----
__device__ float g_win [(size_t)TOK*Cc];       // normalized+shifted windows  [2048*49,192]
__device__ float g_qkv [(size_t)TOK*3*Cc];     // qkv                         [2048*49,576]
__device__ float g_ctx [(size_t)TOK*Cc];       // attention context           [2048*49,192]
__device__ float g_attn[(size_t)TOK*Cc];       // proj output, window-reversed [32*3136,192]

// ============================================================
// Kernel 1: LayerNorm + cyclic shift(-3,-3) + window partition
// one warp per window-token; each lane handles 6 channels
// ============================================================
__global__ void k_ln_part(const float* __restrict__ x,
                          const float* __restrict__ gamma,
                          const float* __restrict__ beta,
                          float* __restrict__ out)
{
    int warp = (blockIdx.x * blockDim.x + threadIdx.x) >> 5;
    int lane = threadIdx.x & 31;
    if (warp >= TOK) return;
    int win = warp / NN, n = warp % NN;
    int bI = win >> 6, wr = win & 63;
    int wh = wr >> 3, ww = wr & 7;
    int hs = wh * WSz + n / WSz;
    int ws = ww * WSz + n % WSz;
    int h = (hs + SHIFT) % Hdim;
    int w = (ws + SHIFT) % Wdim;
    const float* row = x + ((size_t)bI * (Hdim*Wdim) + h * Wdim + w) * Cc;

    float v[6], s = 0.f, s2 = 0.f;
#pragma unroll
    for (int t = 0; t < 6; t++) {
        v[t] = row[lane + 32*t];
        s  += v[t];
        s2 += v[t]*v[t];
    }
#pragma unroll
    for (int o = 16; o; o >>= 1) {
        s  += __shfl_xor_sync(0xffffffffu, s,  o);
        s2 += __shfl_xor_sync(0xffffffffu, s2, o);
    }
    float mu  = s * (1.f/Cc);
    float var = s2 * (1.f/Cc) - mu*mu;
    float inv = rsqrtf(var + 1e-5f);

    float* orow = out + (size_t)warp * Cc;
#pragma unroll
    for (int t = 0; t < 6; t++) {
        int c = lane + 32*t;
        orow[c] = (v[t]-mu)*inv*gamma[c] + beta[c];
    }
}

// ============================================================
// Generic fp32 NT-GEMM: out = A[M,192] @ W[N,192]^T + bias
// tile 64x64, BK=16, 256 threads, 4x4 microtile per thread
// EPI: 0 = plain store (qkv), 1 = window-reverse scatter (proj),
//      2 = gelu + residual (mlp)
// M multiple of 64, N multiple of 64, K = 192 (no guards needed)
// ============================================================
template<int EPI>
__global__ void k_gemm(const float* __restrict__ A,
                       const float* __restrict__ W,
                       const float* __restrict__ bias,
                       float* __restrict__ out,
                       const float* __restrict__ resid,
                       int Ntot)
{
    __shared__ float As[16][64];
    __shared__ float Bs[16][64];
    int tid = threadIdx.x;
    int m0 = blockIdx.x * 64, n0 = blockIdx.y * 64;
    int lm  = tid >> 2;
    int lk4 = (tid & 3) * 4;
    int tx = tid & 15, ty = tid >> 4;

    const float* Aptr = A + (size_t)(m0 + lm) * 192 + lk4;
    const float* Wptr = W + (size_t)(n0 + lm) * 192 + lk4;

    float acc[4][4] = {};
    for (int k0 = 0; k0 < 192; k0 += 16) {
        float4 av = *(const float4*)(Aptr + k0);
        float4 wv = *(const float4*)(Wptr + k0);
        As[lk4+0][lm] = av.x; As[lk4+1][lm] = av.y;
        As[lk4+2][lm] = av.z; As[lk4+3][lm] = av.w;
        Bs[lk4+0][lm] = wv.x; Bs[lk4+1][lm] = wv.y;
        Bs[lk4+2][lm] = wv.z; Bs[lk4+3][lm] = wv.w;
        __syncthreads();
#pragma unroll
        for (int kk = 0; kk < 16; kk++) {
            float a[4], b[4];
#pragma unroll
            for (int i = 0; i < 4; i++) a[i] = As[kk][ty*4+i];
#pragma unroll
            for (int j = 0; j < 4; j++) b[j] = Bs[kk][tx*4+j];
#pragma unroll
            for (int i = 0; i < 4; i++)
#pragma unroll
                for (int j = 0; j < 4; j++)
                    acc[i][j] += a[i]*b[j];
        }
        __syncthreads();
    }

    float bb[4];
#pragma unroll
    for (int j = 0; j < 4; j++) bb[j] = bias[n0 + tx*4 + j];

#pragma unroll
    for (int i = 0; i < 4; i++) {
        int m = m0 + ty*4 + i;
        if (EPI == 0) {
            float* o = out + (size_t)m * Ntot + n0 + tx*4;
#pragma unroll
            for (int j = 0; j < 4; j++) o[j] = acc[i][j] + bb[j];
        } else if (EPI == 1) {
            // window reverse + roll(+3,+3) scatter
            int win = m / NN, n = m % NN;
            int bI = win >> 6, wr = win & 63;
            int wh = wr >> 3, ww = wr & 7;
            int hs = wh*WSz + n/WSz;
            int ws = ww*WSz + n%WSz;
            int dh = (hs + SHIFT) % Hdim;
            int dw = (ws + SHIFT) % Wdim;
            float* o = out + ((size_t)bI*(Hdim*Wdim) + dh*Wdim + dw) * Cc + n0 + tx*4;
#pragma unroll
            for (int j = 0; j < 4; j++) o[j] = acc[i][j] + bb[j];
        } else {
            size_t r = (size_t)m * Cc + n0 + tx*4;
#pragma unroll
            for (int j = 0; j < 4; j++) {
                float y = acc[i][j] + bb[j];
                y = 0.5f * y * (1.f + erff(y * 0.70710678118654752f)); // exact gelu
                out[r + j] = resid[r + j] + y;
            }
        }
    }
}

// ============================================================
// Kernel 3: windowed attention. One block per (window, head).
// 128 threads. q,k,v tiles + 49x49 scores in smem.
// ============================================================
__global__ void k_attn(const float* __restrict__ qkv,
                       const float* __restrict__ table,
                       const int*   __restrict__ rpi,
                       const float* __restrict__ mask,
                       float* __restrict__ ctx)
{
    int win = blockIdx.x;
    int hh  = blockIdx.y;
    int tid = threadIdx.x;

    __shared__ float q[NN][HD+1];
    __shared__ float k[NN][HD+1];
    __shared__ float v[NN][HD+1];
    __shared__ float sc[NN][NN+1];

    const float* base = qkv + (size_t)win * NN * (3*Cc);
    for (int e = tid; e < NN*HD; e += 128) {
        int n = e >> 5, d = e & 31;
        const float* p = base + n*(3*Cc) + hh*HD + d;
        q[n][d] = p[0]      * QSCALE;
        k[n][d] = p[Cc];
        v[n][d] = p[2*Cc];
    }
    __syncthreads();

    int nw = win & 63;
    const float* mrow = mask + (size_t)nw * NN * NN;
    for (int e = tid; e < NN*NN; e += 128) {
        int n = e / NN, m = e % NN;
        float s = 0.f;
#pragma unroll
        for (int d = 0; d < HD; d++) s += q[n][d] * k[m][d];
        s += table[rpi[e]*NHd + hh] + mrow[e];
        sc[n][m] = s;
    }
    __syncthreads();

    if (tid < NN) {
        float mx = -1e30f;
#pragma unroll 7
        for (int m = 0; m < NN; m++) mx = fmaxf(mx, sc[tid][m]);
        float sum = 0.f;
#pragma unroll 7
        for (int m = 0; m < NN; m++) {
            float e = __expf(sc[tid][m] - mx);
            sc[tid][m] = e;
            sum += e;
        }
        float r = 1.f / sum;
#pragma unroll 7
        for (int m = 0; m < NN; m++) sc[tid][m] *= r;
    }
    __syncthreads();

    for (int e = tid; e < NN*HD; e += 128) {
        int n = e >> 5, d = e & 31;
        float s = 0.f;
#pragma unroll 7
        for (int m = 0; m < NN; m++) s += sc[n][m] * v[m][d];
        ctx[(size_t)win * NN * Cc + n*Cc + hh*HD + d] = s;
    }
}

// ============================================================
extern "C" void kernel_launch(void* const* d_in, const int* in_sizes, int n_in,
                              void* d_out, int out_size)
{
    const float* inputs = (const float*)d_in[0];
    const float* mask   = (const float*)d_in[1];
    const float* n1g    = (const float*)d_in[2];
    const float* n1b    = (const float*)d_in[3];
    const float* qkv_w  = (const float*)d_in[4];
    const float* qkv_b  = (const float*)d_in[5];
    const float* table  = (const float*)d_in[6];
    const int*   rpi    = (const int*)  d_in[7];
    const float* proj_w = (const float*)d_in[8];
    const float* proj_b = (const float*)d_in[9];
    const float* lin_w  = (const float*)d_in[10];
    const float* lin_b  = (const float*)d_in[11];
    float* out = (float*)d_out;

    float *p_win, *p_qkv, *p_ctx, *p_attn;
    cudaGetSymbolAddress((void**)&p_win,  g_win);
    cudaGetSymbolAddress((void**)&p_qkv,  g_qkv);
    cudaGetSymbolAddress((void**)&p_ctx,  g_ctx);
    cudaGetSymbolAddress((void**)&p_attn, g_attn);

    // 1. LN + shift + partition
    {
        int warps = TOK;
        int blocks = (warps*32 + 255) / 256;
        k_ln_part<<<blocks, 256>>>(inputs, n1g, n1b, p_win);
    }
    // 2. QKV GEMM: [100352,192] @ [576,192]^T
    {
        dim3 grid(TOK/64, (3*Cc)/64);
        k_gemm<0><<<grid, 256>>>(p_win, qkv_w, qkv_b, p_qkv, nullptr, 3*Cc);
    }
    // 3. Attention per (window, head)
    {
        dim3 grid(BWIN, NHd);
        k_attn<<<grid, 128>>>(p_qkv, table, rpi, mask, p_ctx);
    }
    // 4. Proj GEMM + window reverse scatter
    {
        dim3 grid(TOK/64, Cc/64);
        k_gemm<1><<<grid, 256>>>(p_ctx, proj_w, proj_b, p_attn, nullptr, Cc);
    }
    // 5. MLP GEMM + exact gelu + residual
    {
        dim3 grid(TOK/64, Cc/64);
        k_gemm<2><<<grid, 256>>>(p_attn, lin_w, lin_b, out, inputs, Cc);
    }
}

// round 5
// speedup vs baseline: 1.9652x; 1.9652x over previous
#include <cuda_runtime.h>
#include <math.h>
#include <stdint.h>

#define Bsz   32
#define Hdim  56
#define Wdim  56
#define Cc    192
#define WSz   7
#define SHIFT 3
#define NHd   6
#define HD    32
#define NN    49
#define NWIN  64
#define BWIN  (Bsz*NWIN)    // 2048
#define TOK   (BWIN*NN)     // 100352
#define QSCALE 0.17677669529663689f

// ---- scratch (device globals; no allocation allowed) ----
__device__ float g_win [(size_t)TOK*Cc];
__device__ float g_qkv [(size_t)TOK*3*Cc];
__device__ float g_ctx [(size_t)TOK*Cc];
__device__ float g_attn[(size_t)TOK*Cc];

// ============================================================
// Kernel 1: LayerNorm + cyclic shift(-3,-3) + window partition
// ============================================================
__global__ void k_ln_part(const float* __restrict__ x,
                          const float* __restrict__ gamma,
                          const float* __restrict__ beta,
                          float* __restrict__ out)
{
    int warp = (blockIdx.x * blockDim.x + threadIdx.x) >> 5;
    int lane = threadIdx.x & 31;
    if (warp >= TOK) return;
    int win = warp / NN, n = warp % NN;
    int bI = win >> 6, wr = win & 63;
    int wh = wr >> 3, ww = wr & 7;
    int hs = wh * WSz + n / WSz;
    int ws = ww * WSz + n % WSz;
    int h = (hs + SHIFT) % Hdim;
    int w = (ws + SHIFT) % Wdim;
    const float* row = x + ((size_t)bI * (Hdim*Wdim) + h * Wdim + w) * Cc;

    float v[6], s = 0.f, s2 = 0.f;
#pragma unroll
    for (int t = 0; t < 6; t++) {
        v[t] = row[lane + 32*t];
        s  += v[t];
        s2 += v[t]*v[t];
    }
#pragma unroll
    for (int o = 16; o; o >>= 1) {
        s  += __shfl_xor_sync(0xffffffffu, s,  o);
        s2 += __shfl_xor_sync(0xffffffffu, s2, o);
    }
    float mu  = s * (1.f/Cc);
    float var = s2 * (1.f/Cc) - mu*mu;
    float inv = rsqrtf(var + 1e-5f);

    float* orow = out + (size_t)warp * Cc;
#pragma unroll
    for (int t = 0; t < 6; t++) {
        int c = lane + 32*t;
        orow[c] = (v[t]-mu)*inv*gamma[c] + beta[c];
    }
}

// ============================================================
// TF32 tensor-core NT-GEMM: out = A[M,192] @ W[N,192]^T + bias
// BM=128 BN=64 BK=16, 256 threads (8 warps, 4x2), warp = 32x32
// EPI: 0 plain, 1 window-reverse scatter, 2 gelu+residual
// ============================================================
__device__ __forceinline__ uint32_t f2tf32(float x) {
    uint32_t r;
    asm("cvt.rna.tf32.f32 %0, %1;" : "=r"(r) : "f"(x));
    return r;
}
__device__ __forceinline__ void mma_tf32(float c[4], const uint32_t a[4], const uint32_t b[2]) {
    asm volatile("mma.sync.aligned.m16n8k8.row.col.f32.tf32.tf32.f32 "
        "{%0,%1,%2,%3}, {%4,%5,%6,%7}, {%8,%9}, {%0,%1,%2,%3};"
        : "+f"(c[0]), "+f"(c[1]), "+f"(c[2]), "+f"(c[3])
        : "r"(a[0]), "r"(a[1]), "r"(a[2]), "r"(a[3]), "r"(b[0]), "r"(b[1]));
}

template<int EPI>
__global__ __launch_bounds__(256) void k_gemm_tc(
        const float* __restrict__ A,
        const float* __restrict__ W,
        const float* __restrict__ bias,
        float* __restrict__ out,
        const float* __restrict__ resid,
        int Ntot)
{
    __shared__ float As[128][20];
    __shared__ float Bs[64][20];
    int tid  = threadIdx.x;
    int lane = tid & 31;
    int w    = tid >> 5;
    int wm   = (w & 3) * 32;
    int wn   = (w >> 2) * 32;
    int m0 = blockIdx.x * 128, n0 = blockIdx.y * 64;

    int ar = tid >> 2;          // 0..63
    int ac = (tid & 3) * 4;     // 0,4,8,12
    const float* Ap  = A + (size_t)(m0 + ar) * 192 + ac;
    const float* Ap2 = Ap + (size_t)64 * 192;
    const float* Wp  = W + (size_t)(n0 + ar) * 192 + ac;

    float c[2][4][4];
#pragma unroll
    for (int mt = 0; mt < 2; mt++)
#pragma unroll
        for (int nt = 0; nt < 4; nt++)
#pragma unroll
            for (int i = 0; i < 4; i++) c[mt][nt][i] = 0.f;

    int r = lane >> 2, q = lane & 3;

    for (int k0 = 0; k0 < 192; k0 += 16) {
        float4 a1 = *(const float4*)(Ap + k0);
        float4 a2 = *(const float4*)(Ap2 + k0);
        float4 b1 = *(const float4*)(Wp + k0);
        As[ar][ac+0]    = __uint_as_float(f2tf32(a1.x));
        As[ar][ac+1]    = __uint_as_float(f2tf32(a1.y));
        As[ar][ac+2]    = __uint_as_float(f2tf32(a1.z));
        As[ar][ac+3]    = __uint_as_float(f2tf32(a1.w));
        As[ar+64][ac+0] = __uint_as_float(f2tf32(a2.x));
        As[ar+64][ac+1] = __uint_as_float(f2tf32(a2.y));
        As[ar+64][ac+2] = __uint_as_float(f2tf32(a2.z));
        As[ar+64][ac+3] = __uint_as_float(f2tf32(a2.w));
        Bs[ar][ac+0]    = __uint_as_float(f2tf32(b1.x));
        Bs[ar][ac+1]    = __uint_as_float(f2tf32(b1.y));
        Bs[ar][ac+2]    = __uint_as_float(f2tf32(b1.z));
        Bs[ar][ac+3]    = __uint_as_float(f2tf32(b1.w));
        __syncthreads();

#pragma unroll
        for (int kk = 0; kk < 16; kk += 8) {
            uint32_t af[2][4], bf[4][2];
#pragma unroll
            for (int mt = 0; mt < 2; mt++) {
                int mr = wm + mt*16 + r;
                af[mt][0] = __float_as_uint(As[mr    ][kk+q  ]);
                af[mt][1] = __float_as_uint(As[mr + 8][kk+q  ]);
                af[mt][2] = __float_as_uint(As[mr    ][kk+q+4]);
                af[mt][3] = __float_as_uint(As[mr + 8][kk+q+4]);
            }
#pragma unroll
            for (int nt = 0; nt < 4; nt++) {
                int nr = wn + nt*8 + r;
                bf[nt][0] = __float_as_uint(Bs[nr][kk+q  ]);
                bf[nt][1] = __float_as_uint(Bs[nr][kk+q+4]);
            }
#pragma unroll
            for (int mt = 0; mt < 2; mt++)
#pragma unroll
                for (int nt = 0; nt < 4; nt++)
                    mma_tf32(c[mt][nt], af[mt], bf[nt]);
        }
        __syncthreads();
    }

    // epilogue
    int q2 = q * 2;
    float bb[4][2];
#pragma unroll
    for (int nt = 0; nt < 4; nt++) {
        bb[nt][0] = bias[n0 + wn + nt*8 + q2];
        bb[nt][1] = bias[n0 + wn + nt*8 + q2 + 1];
    }

#pragma unroll
    for (int mt = 0; mt < 2; mt++)
#pragma unroll
    for (int half = 0; half < 2; half++) {
        int m = m0 + wm + mt*16 + r + half*8;
        float* orow;
        const float* rrow = nullptr;
        if (EPI == 1) {
            int win = m / NN, n = m % NN;
            int bI = win >> 6, wr = win & 63;
            int wh = wr >> 3, ww = wr & 7;
            int hs = wh*WSz + n/WSz;
            int ws = ww*WSz + n%WSz;
            int dh = (hs + SHIFT) % Hdim;
            int dw = (ws + SHIFT) % Wdim;
            orow = out + ((size_t)bI*(Hdim*Wdim) + dh*Wdim + dw)*Cc + n0 + wn;
        } else {
            orow = out + (size_t)m * Ntot + n0 + wn;
            if (EPI == 2) rrow = resid + (size_t)m * Cc + n0 + wn;
        }
#pragma unroll
        for (int nt = 0; nt < 4; nt++) {
            float x0 = c[mt][nt][half*2+0] + bb[nt][0];
            float x1 = c[mt][nt][half*2+1] + bb[nt][1];
            if (EPI == 2) {
                x0 = 0.5f*x0*(1.f + erff(x0*0.70710678118654752f));
                x1 = 0.5f*x1*(1.f + erff(x1*0.70710678118654752f));
                x0 += rrow[nt*8 + q2];
                x1 += rrow[nt*8 + q2 + 1];
            }
            *(float2*)(orow + nt*8 + q2) = make_float2(x0, x1);
        }
    }
}

// ============================================================
// Kernel 3: windowed attention, one block per (window, head)
// ============================================================
__global__ void k_attn(const float* __restrict__ qkv,
                       const float* __restrict__ table,
                       const int*   __restrict__ rpi,
                       const float* __restrict__ mask,
                       float* __restrict__ ctx)
{
    int win = blockIdx.x;
    int hh  = blockIdx.y;
    int tid = threadIdx.x;

    __shared__ __align__(16) float qs[NN][36];   // stride 36 floats = 144B
    __shared__ __align__(16) float ks[NN][36];
    __shared__ __align__(16) float vs[NN][36];
    __shared__ float sc[NN][NN+1];

    const float* base = qkv + (size_t)win * NN * (3*Cc);
    for (int e = tid; e < NN*HD; e += 128) {
        int n = e >> 5, d = e & 31;
        const float* p = base + n*(3*Cc) + hh*HD + d;
        qs[n][d] = p[0]    * QSCALE;
        ks[n][d] = p[Cc];
        vs[n][d] = p[2*Cc];
    }
    __syncthreads();

    int nw = win & 63;
    const float* mrow = mask + (size_t)nw * NN * NN;

    // QK^T + bias + mask: thread handles half a row, q cached in regs
    if (tid < 98) {
        int n = tid >> 1;
        int m_lo = (tid & 1) ? 25 : 0;
        int m_hi = (tid & 1) ? 49 : 25;
        float4 qr[8];
        const float4* qp = (const float4*)&qs[n][0];
#pragma unroll
        for (int d = 0; d < 8; d++) qr[d] = qp[d];
        for (int m = m_lo; m < m_hi; m++) {
            const float4* kp = (const float4*)&ks[m][0];
            float s = 0.f;
#pragma unroll
            for (int d = 0; d < 8; d++) {
                float4 kv = kp[d];
                s += qr[d].x*kv.x + qr[d].y*kv.y + qr[d].z*kv.z + qr[d].w*kv.w;
            }
            int e = n*NN + m;
            s += table[rpi[e]*NHd + hh] + mrow[e];
            sc[n][m] = s;
        }
    }
    __syncthreads();

    // softmax per row
    if (tid < NN) {
        float mx = -1e30f;
#pragma unroll 7
        for (int m = 0; m < NN; m++) mx = fmaxf(mx, sc[tid][m]);
        float sum = 0.f;
#pragma unroll 7
        for (int m = 0; m < NN; m++) {
            float e = __expf(sc[tid][m] - mx);
            sc[tid][m] = e;
            sum += e;
        }
        float rs = 1.f / sum;
#pragma unroll 7
        for (int m = 0; m < NN; m++) sc[tid][m] *= rs;
    }
    __syncthreads();

    // P @ V, vectorized over d (float4)
    for (int e = tid; e < NN*(HD/4); e += 128) {
        int n = e >> 3, d4 = e & 7;
        float4 acc = make_float4(0.f, 0.f, 0.f, 0.f);
#pragma unroll 7
        for (int m = 0; m < NN; m++) {
            float p = sc[n][m];
            float4 vv = *(const float4*)&vs[m][d4*4];
            acc.x += p*vv.x; acc.y += p*vv.y; acc.z += p*vv.z; acc.w += p*vv.w;
        }
        *(float4*)(ctx + (size_t)win*NN*Cc + n*Cc + hh*HD + d4*4) = acc;
    }
}

// ============================================================
extern "C" void kernel_launch(void* const* d_in, const int* in_sizes, int n_in,
                              void* d_out, int out_size)
{
    const float* inputs = (const float*)d_in[0];
    const float* mask   = (const float*)d_in[1];
    const float* n1g    = (const float*)d_in[2];
    const float* n1b    = (const float*)d_in[3];
    const float* qkv_w  = (const float*)d_in[4];
    const float* qkv_b  = (const float*)d_in[5];
    const float* table  = (const float*)d_in[6];
    const int*   rpi    = (const int*)  d_in[7];
    const float* proj_w = (const float*)d_in[8];
    const float* proj_b = (const float*)d_in[9];
    const float* lin_w  = (const float*)d_in[10];
    const float* lin_b  = (const float*)d_in[11];
    float* out = (float*)d_out;

    float *p_win, *p_qkv, *p_ctx, *p_attn;
    cudaGetSymbolAddress((void**)&p_win,  g_win);
    cudaGetSymbolAddress((void**)&p_qkv,  g_qkv);
    cudaGetSymbolAddress((void**)&p_ctx,  g_ctx);
    cudaGetSymbolAddress((void**)&p_attn, g_attn);

    // 1. LN + shift + partition
    k_ln_part<<<(TOK*32 + 255)/256, 256>>>(inputs, n1g, n1b, p_win);

    // 2. QKV GEMM: [100352,192] @ [576,192]^T
    {
        dim3 grid(TOK/128, (3*Cc)/64);
        k_gemm_tc<0><<<grid, 256>>>(p_win, qkv_w, qkv_b, p_qkv, nullptr, 3*Cc);
    }
    // 3. Attention
    {
        dim3 grid(BWIN, NHd);
        k_attn<<<grid, 128>>>(p_qkv, table, rpi, mask, p_ctx);
    }
    // 4. Proj GEMM + window reverse scatter
    {
        dim3 grid(TOK/128, Cc/64);
        k_gemm_tc<1><<<grid, 256>>>(p_ctx, proj_w, proj_b, p_attn, nullptr, Cc);
    }
    // 5. MLP GEMM + exact gelu + residual
    {
        dim3 grid(TOK/128, Cc/64);
        k_gemm_tc<2><<<grid, 256>>>(p_attn, lin_w, lin_b, out, inputs, Cc);
    }
}

// round 6
// speedup vs baseline: 2.8551x; 1.4528x over previous
#include <cuda_runtime.h>
#include <cuda_bf16.h>
#include <math.h>
#include <stdint.h>

#define Bsz   32
#define Hdim  56
#define Wdim  56
#define Cc    192
#define WSz   7
#define SHIFT 3
#define NHd   6
#define HD    32
#define NN    49
#define NWIN  64
#define BWIN  (Bsz*NWIN)    // 2048
#define TOK   (BWIN*NN)     // 100352
#define QSCALE 0.17677669529663689f

// ---- scratch (device globals; no allocation allowed) ----
__device__ __nv_bfloat16 g_win [(size_t)TOK*Cc];
__device__ __nv_bfloat16 g_qkv [(size_t)TOK*3*Cc];
__device__ __nv_bfloat16 g_ctx [(size_t)TOK*Cc];
__device__ __nv_bfloat16 g_attn[(size_t)TOK*Cc];
__device__ __nv_bfloat16 g_wq  [576*192];
__device__ __nv_bfloat16 g_wp  [192*192];
__device__ __nv_bfloat16 g_wl  [192*192];

// ============================================================
// Kernel 0: convert weights fp32 -> bf16 (once per launch)
// ============================================================
__global__ void k_cvt(const float* __restrict__ wq,
                      const float* __restrict__ wp,
                      const float* __restrict__ wl)
{
    int i = blockIdx.x * blockDim.x + threadIdx.x;
    if (i < 576*192) g_wq[i] = __float2bfloat16(wq[i]);
    if (i < 192*192) {
        g_wp[i] = __float2bfloat16(wp[i]);
        g_wl[i] = __float2bfloat16(wl[i]);
    }
}

// ============================================================
// Kernel 1: LayerNorm + cyclic shift(-3,-3) + window partition
// ============================================================
__global__ void k_ln_part(const float* __restrict__ x,
                          const float* __restrict__ gamma,
                          const float* __restrict__ beta,
                          __nv_bfloat16* __restrict__ out)
{
    int warp = (blockIdx.x * blockDim.x + threadIdx.x) >> 5;
    int lane = threadIdx.x & 31;
    if (warp >= TOK) return;
    int win = warp / NN, n = warp % NN;
    int bI = win >> 6, wr = win & 63;
    int wh = wr >> 3, ww = wr & 7;
    int hs = wh * WSz + n / WSz;
    int ws = ww * WSz + n % WSz;
    int h = (hs + SHIFT) % Hdim;
    int w = (ws + SHIFT) % Wdim;
    const float* row = x + ((size_t)bI * (Hdim*Wdim) + h * Wdim + w) * Cc;

    float v[6], s = 0.f, s2 = 0.f;
#pragma unroll
    for (int t = 0; t < 6; t++) {
        v[t] = row[lane + 32*t];
        s  += v[t];
        s2 += v[t]*v[t];
    }
#pragma unroll
    for (int o = 16; o; o >>= 1) {
        s  += __shfl_xor_sync(0xffffffffu, s,  o);
        s2 += __shfl_xor_sync(0xffffffffu, s2, o);
    }
    float mu  = s * (1.f/Cc);
    float var = s2 * (1.f/Cc) - mu*mu;
    float inv = rsqrtf(var + 1e-5f);

    __nv_bfloat16* orow = out + (size_t)warp * Cc;
#pragma unroll
    for (int t = 0; t < 6; t++) {
        int c = lane + 32*t;
        orow[c] = __float2bfloat16((v[t]-mu)*inv*gamma[c] + beta[c]);
    }
}

// ============================================================
// BF16 tensor-core NT-GEMM with ldmatrix + cp.async 2-stage
// out = A[M,192] @ W[N,192]^T + bias
// BM=64 BN=192 BK=32, 256 threads (8 warps 2x4), warp = 32x48
// EPI: 0 plain bf16, 1 window-reverse scatter bf16, 2 gelu+resid fp32
// smem: 16B chunk swizzle, slot(c8,r) = c8 ^ ((r>>1)&3)
// ============================================================
__device__ __forceinline__ uint32_t swzoff(int r, int c8) {  // in bf16 elems
    return (uint32_t)(r*32 + ((c8 ^ ((r>>1)&3)) << 3));
}
__device__ __forceinline__ void ldsm4(uint32_t f[4], uint32_t addr) {
    asm volatile("ldmatrix.sync.aligned.m8n8.x4.shared.b16 {%0,%1,%2,%3}, [%4];"
        : "=r"(f[0]), "=r"(f[1]), "=r"(f[2]), "=r"(f[3]) : "r"(addr));
}
__device__ __forceinline__ void mma_bf16(float c[4], const uint32_t a[4],
                                         uint32_t b0, uint32_t b1) {
    asm volatile("mma.sync.aligned.m16n8k16.row.col.f32.bf16.bf16.f32 "
        "{%0,%1,%2,%3}, {%4,%5,%6,%7}, {%8,%9}, {%0,%1,%2,%3};"
        : "+f"(c[0]), "+f"(c[1]), "+f"(c[2]), "+f"(c[3])
        : "r"(a[0]), "r"(a[1]), "r"(a[2]), "r"(a[3]), "r"(b0), "r"(b1));
}
__device__ __forceinline__ void cp16(uint32_t dst, const void* src) {
    asm volatile("cp.async.cg.shared.global [%0], [%1], 16;" :: "r"(dst), "l"(src));
}

template<int EPI>
__global__ __launch_bounds__(256) void k_gemm_bf16(
        const __nv_bfloat16* __restrict__ A,
        const __nv_bfloat16* __restrict__ W,
        const float* __restrict__ bias,
        void* __restrict__ outv,
        const float* __restrict__ resid,
        int Ntot)
{
    __shared__ __align__(16) __nv_bfloat16 As[2][64*32];
    __shared__ __align__(16) __nv_bfloat16 Bs[2][192*32];
    int tid = threadIdx.x, lane = tid & 31, w = tid >> 5;
    int wm = (w & 1) * 32, wn = (w >> 1) * 48;
    int m0 = blockIdx.x * 64, n0 = blockIdx.y * 192;

    uint32_t sA = (uint32_t)__cvta_generic_to_shared(&As[0][0]);
    uint32_t sB = (uint32_t)__cvta_generic_to_shared(&Bs[0][0]);
    const uint32_t stgA = 64*32*2, stgB = 192*32*2;

    // load coords (16B chunks)
    int arow = tid >> 2, aslot = tid & 3;
    const __nv_bfloat16* asrc = A + (size_t)(m0 + arow)*192 + aslot*8;
    uint32_t adst = sA + 2*swzoff(arow, aslot);
    const __nv_bfloat16* bsrc[3];
    uint32_t bdst[3];
#pragma unroll
    for (int p = 0; p < 3; p++) {
        int i = tid + p*256;
        int br = i >> 2, bs = i & 3;
        bsrc[p] = W + (size_t)(n0 + br)*192 + bs*8;
        bdst[p] = sB + 2*swzoff(br, bs);
    }

    float acc[2][6][4];
#pragma unroll
    for (int mt = 0; mt < 2; mt++)
#pragma unroll
        for (int nt = 0; nt < 6; nt++)
#pragma unroll
            for (int i = 0; i < 4; i++) acc[mt][nt][i] = 0.f;

    // prefetch stage 0 (k0 = 0)
    cp16(adst, asrc);
#pragma unroll
    for (int p = 0; p < 3; p++) cp16(bdst[p], bsrc[p]);
    asm volatile("cp.async.commit_group;");

    for (int it = 0; it < 6; it++) {
        asm volatile("cp.async.wait_group 0;");
        __syncthreads();
        if (it + 1 < 6) {
            int st = (it + 1) & 1;
            int koff = (it + 1) * 32;
            cp16(adst + st*stgA, asrc + koff);
#pragma unroll
            for (int p = 0; p < 3; p++) cp16(bdst[p] + st*stgB, bsrc[p] + koff);
            asm volatile("cp.async.commit_group;");
        }
        // compute from stage it&1
        uint32_t baseA = sA + (it & 1)*stgA;
        uint32_t baseB = sB + (it & 1)*stgB;
#pragma unroll
        for (int kk8 = 0; kk8 < 4; kk8 += 2) {
            uint32_t af[2][4];
#pragma unroll
            for (int mh = 0; mh < 2; mh++) {
                int row = wm + mh*16 + (lane & 15);
                int c8  = kk8 + (lane >> 4);
                ldsm4(af[mh], baseA + 2*swzoff(row, c8));
            }
            uint32_t bf[3][4];
#pragma unroll
            for (int nh = 0; nh < 3; nh++) {
                int row = wn + nh*16 + ((lane >> 4) << 3) + (lane & 7);
                int c8  = kk8 + ((lane >> 3) & 1);
                ldsm4(bf[nh], baseB + 2*swzoff(row, c8));
            }
#pragma unroll
            for (int mt = 0; mt < 2; mt++)
#pragma unroll
                for (int nt = 0; nt < 6; nt++)
                    mma_bf16(acc[mt][nt], af[mt],
                             bf[nt >> 1][(nt & 1)*2], bf[nt >> 1][(nt & 1)*2 + 1]);
        }
        __syncthreads();
    }

    // epilogue
    int r = lane >> 2, q2 = (lane & 3) * 2;
    float bb[6][2];
#pragma unroll
    for (int nt = 0; nt < 6; nt++) {
        bb[nt][0] = bias[n0 + wn + nt*8 + q2];
        bb[nt][1] = bias[n0 + wn + nt*8 + q2 + 1];
    }

#pragma unroll
    for (int mt = 0; mt < 2; mt++)
#pragma unroll
    for (int half = 0; half < 2; half++) {
        int m = m0 + wm + mt*16 + r + half*8;
        if (EPI == 0) {
            __nv_bfloat16* orow = (__nv_bfloat16*)outv + (size_t)m*Ntot + n0 + wn;
#pragma unroll
            for (int nt = 0; nt < 6; nt++) {
                float x0 = acc[mt][nt][half*2+0] + bb[nt][0];
                float x1 = acc[mt][nt][half*2+1] + bb[nt][1];
                *(__nv_bfloat162*)(orow + nt*8 + q2) = __floats2bfloat162_rn(x0, x1);
            }
        } else if (EPI == 1) {
            int win = m / NN, n = m % NN;
            int bI = win >> 6, wr = win & 63;
            int wh = wr >> 3, ww = wr & 7;
            int hs = wh*WSz + n/WSz;
            int ws = ww*WSz + n%WSz;
            int dh = (hs + SHIFT) % Hdim;
            int dw = (ws + SHIFT) % Wdim;
            __nv_bfloat16* orow = (__nv_bfloat16*)outv +
                ((size_t)bI*(Hdim*Wdim) + dh*Wdim + dw)*Cc + n0 + wn;
#pragma unroll
            for (int nt = 0; nt < 6; nt++) {
                float x0 = acc[mt][nt][half*2+0] + bb[nt][0];
                float x1 = acc[mt][nt][half*2+1] + bb[nt][1];
                *(__nv_bfloat162*)(orow + nt*8 + q2) = __floats2bfloat162_rn(x0, x1);
            }
        } else {
            float* orow = (float*)outv + (size_t)m*Cc + n0 + wn;
            const float* rrow = resid + (size_t)m*Cc + n0 + wn;
#pragma unroll
            for (int nt = 0; nt < 6; nt++) {
                float x0 = acc[mt][nt][half*2+0] + bb[nt][0];
                float x1 = acc[mt][nt][half*2+1] + bb[nt][1];
                x0 = 0.5f*x0*(1.f + erff(x0*0.70710678118654752f));
                x1 = 0.5f*x1*(1.f + erff(x1*0.70710678118654752f));
                x0 += rrow[nt*8 + q2];
                x1 += rrow[nt*8 + q2 + 1];
                *(float2*)(orow + nt*8 + q2) = make_float2(x0, x1);
            }
        }
    }
}

// ============================================================
// Kernel 3: windowed attention, one block per (window, head)
// bf16 in / bf16 out, fp32 compute in smem
// ============================================================
__global__ void k_attn(const __nv_bfloat16* __restrict__ qkv,
                       const float* __restrict__ table,
                       const int*   __restrict__ rpi,
                       const float* __restrict__ mask,
                       __nv_bfloat16* __restrict__ ctx)
{
    int win = blockIdx.x;
    int hh  = blockIdx.y;
    int tid = threadIdx.x;

    __shared__ __align__(16) float qs[NN][36];
    __shared__ __align__(16) float ks[NN][36];
    __shared__ __align__(16) float vs[NN][36];
    __shared__ float sc[NN][NN+1];

    const __nv_bfloat16* base = qkv + (size_t)win * NN * (3*Cc);
    for (int e = tid; e < NN*16; e += 128) {
        int n = e >> 4, d2 = e & 15;
        const __nv_bfloat16* p = base + n*(3*Cc) + hh*HD + d2*2;
        float2 qv = __bfloat1622float2(*(const __nv_bfloat162*)p);
        float2 kv = __bfloat1622float2(*(const __nv_bfloat162*)(p + Cc));
        float2 vv = __bfloat1622float2(*(const __nv_bfloat162*)(p + 2*Cc));
        qs[n][d2*2]   = qv.x * QSCALE;
        qs[n][d2*2+1] = qv.y * QSCALE;
        ks[n][d2*2]   = kv.x;
        ks[n][d2*2+1] = kv.y;
        vs[n][d2*2]   = vv.x;
        vs[n][d2*2+1] = vv.y;
    }
    __syncthreads();

    int nw = win & 63;
    const float* mrow = mask + (size_t)nw * NN * NN;

    if (tid < 98) {
        int n = tid >> 1;
        int m_lo = (tid & 1) ? 25 : 0;
        int m_hi = (tid & 1) ? 49 : 25;
        float4 qr[8];
        const float4* qp = (const float4*)&qs[n][0];
#pragma unroll
        for (int d = 0; d < 8; d++) qr[d] = qp[d];
        for (int m = m_lo; m < m_hi; m++) {
            const float4* kp = (const float4*)&ks[m][0];
            float s = 0.f;
#pragma unroll
            for (int d = 0; d < 8; d++) {
                float4 kv = kp[d];
                s += qr[d].x*kv.x + qr[d].y*kv.y + qr[d].z*kv.z + qr[d].w*kv.w;
            }
            int e = n*NN + m;
            s += table[rpi[e]*NHd + hh] + mrow[e];
            sc[n][m] = s;
        }
    }
    __syncthreads();

    if (tid < NN) {
        float mx = -1e30f;
#pragma unroll 7
        for (int m = 0; m < NN; m++) mx = fmaxf(mx, sc[tid][m]);
        float sum = 0.f;
#pragma unroll 7
        for (int m = 0; m < NN; m++) {
            float e = __expf(sc[tid][m] - mx);
            sc[tid][m] = e;
            sum += e;
        }
        float rs = 1.f / sum;
#pragma unroll 7
        for (int m = 0; m < NN; m++) sc[tid][m] *= rs;
    }
    __syncthreads();

    for (int e = tid; e < NN*(HD/4); e += 128) {
        int n = e >> 3, d4 = e & 7;
        float4 acc = make_float4(0.f, 0.f, 0.f, 0.f);
#pragma unroll 7
        for (int m = 0; m < NN; m++) {
            float p = sc[n][m];
            float4 vv = *(const float4*)&vs[m][d4*4];
            acc.x += p*vv.x; acc.y += p*vv.y; acc.z += p*vv.z; acc.w += p*vv.w;
        }
        __nv_bfloat16* cp_ = ctx + (size_t)win*NN*Cc + n*Cc + hh*HD + d4*4;
        *(__nv_bfloat162*)(cp_)     = __floats2bfloat162_rn(acc.x, acc.y);
        *(__nv_bfloat162*)(cp_ + 2) = __floats2bfloat162_rn(acc.z, acc.w);
    }
}

// ============================================================
extern "C" void kernel_launch(void* const* d_in, const int* in_sizes, int n_in,
                              void* d_out, int out_size)
{
    const float* inputs = (const float*)d_in[0];
    const float* mask   = (const float*)d_in[1];
    const float* n1g    = (const float*)d_in[2];
    const float* n1b    = (const float*)d_in[3];
    const float* qkv_w  = (const float*)d_in[4];
    const float* qkv_b  = (const float*)d_in[5];
    const float* table  = (const float*)d_in[6];
    const int*   rpi    = (const int*)  d_in[7];
    const float* proj_w = (const float*)d_in[8];
    const float* proj_b = (const float*)d_in[9];
    const float* lin_w  = (const float*)d_in[10];
    const float* lin_b  = (const float*)d_in[11];
    float* out = (float*)d_out;

    __nv_bfloat16 *p_win, *p_qkv, *p_ctx, *p_attn, *p_wq, *p_wp, *p_wl;
    cudaGetSymbolAddress((void**)&p_win,  g_win);
    cudaGetSymbolAddress((void**)&p_qkv,  g_qkv);
    cudaGetSymbolAddress((void**)&p_ctx,  g_ctx);
    cudaGetSymbolAddress((void**)&p_attn, g_attn);
    cudaGetSymbolAddress((void**)&p_wq,   g_wq);
    cudaGetSymbolAddress((void**)&p_wp,   g_wp);
    cudaGetSymbolAddress((void**)&p_wl,   g_wl);

    // 0. weight conversion fp32 -> bf16
    k_cvt<<<(576*192 + 255)/256, 256>>>(qkv_w, proj_w, lin_w);

    // 1. LN + shift + partition (bf16 out)
    k_ln_part<<<(TOK*32 + 255)/256, 256>>>(inputs, n1g, n1b, p_win);

    // 2. QKV GEMM: [100352,192] @ [576,192]^T -> bf16
    {
        dim3 grid(TOK/64, 3);
        k_gemm_bf16<0><<<grid, 256>>>(p_win, p_wq, qkv_b, p_qkv, nullptr, 3*Cc);
    }
    // 3. Attention
    {
        dim3 grid(BWIN, NHd);
        k_attn<<<grid, 128>>>(p_qkv, table, rpi, mask, p_ctx);
    }
    // 4. Proj GEMM + window reverse scatter -> bf16
    {
        dim3 grid(TOK/64, 1);
        k_gemm_bf16<1><<<grid, 256>>>(p_ctx, p_wp, proj_b, p_attn, nullptr, Cc);
    }
    // 5. MLP GEMM + exact gelu + residual -> fp32 out
    {
        dim3 grid(TOK/64, 1);
        k_gemm_bf16<2><<<grid, 256>>>(p_attn, p_wl, lin_b, out, inputs, Cc);
    }
}

// round 7
// speedup vs baseline: 3.8582x; 1.3513x over previous
#include <cuda_runtime.h>
#include <cuda_bf16.h>
#include <math.h>
#include <stdint.h>

#define Bsz   32
#define Hdim  56
#define Wdim  56
#define Cc    192
#define WSz   7
#define SHIFT 3
#define NHd   6
#define HD    32
#define NN    49
#define NWIN  64
#define BWIN  (Bsz*NWIN)    // 2048
#define TOK   (BWIN*NN)     // 100352
#define QSCALE 0.17677669529663689f

// ---- scratch (device globals; no allocation allowed) ----
__device__ __nv_bfloat16 g_win [(size_t)TOK*Cc];
__device__ __nv_bfloat16 g_qkv [(size_t)TOK*3*Cc];
__device__ __nv_bfloat16 g_ctx [(size_t)TOK*Cc];
__device__ __nv_bfloat16 g_attn[(size_t)TOK*Cc];
__device__ __nv_bfloat16 g_wq  [576*192];
__device__ __nv_bfloat16 g_wp  [192*192];
__device__ __nv_bfloat16 g_wl  [192*192];
__device__ float         g_biasH[6*NN*NN];   // bias gather per head

// ============================================================
// Kernel 0: convert weights fp32 -> bf16, precompute head bias
// ============================================================
__global__ void k_cvt(const float* __restrict__ wq,
                      const float* __restrict__ wp,
                      const float* __restrict__ wl,
                      const float* __restrict__ table,
                      const int*   __restrict__ rpi)
{
    int i = blockIdx.x * blockDim.x + threadIdx.x;
    if (i < 576*192) g_wq[i] = __float2bfloat16(wq[i]);
    if (i < 192*192) {
        g_wp[i] = __float2bfloat16(wp[i]);
        g_wl[i] = __float2bfloat16(wl[i]);
    }
    if (i < 6*NN*NN) {
        int h = i / (NN*NN), e = i % (NN*NN);
        g_biasH[i] = table[rpi[e]*NHd + h];
    }
}

// ============================================================
// Kernel 1: LayerNorm + cyclic shift(-3,-3) + window partition
// ============================================================
__global__ void k_ln_part(const float* __restrict__ x,
                          const float* __restrict__ gamma,
                          const float* __restrict__ beta,
                          __nv_bfloat16* __restrict__ out)
{
    int warp = (blockIdx.x * blockDim.x + threadIdx.x) >> 5;
    int lane = threadIdx.x & 31;
    if (warp >= TOK) return;
    int win = warp / NN, n = warp % NN;
    int bI = win >> 6, wr = win & 63;
    int wh = wr >> 3, ww = wr & 7;
    int hs = wh * WSz + n / WSz;
    int ws = ww * WSz + n % WSz;
    int h = (hs + SHIFT) % Hdim;
    int w = (ws + SHIFT) % Wdim;
    const float* row = x + ((size_t)bI * (Hdim*Wdim) + h * Wdim + w) * Cc;

    float v[6], s = 0.f, s2 = 0.f;
#pragma unroll
    for (int t = 0; t < 6; t++) {
        v[t] = row[lane + 32*t];
        s  += v[t];
        s2 += v[t]*v[t];
    }
#pragma unroll
    for (int o = 16; o; o >>= 1) {
        s  += __shfl_xor_sync(0xffffffffu, s,  o);
        s2 += __shfl_xor_sync(0xffffffffu, s2, o);
    }
    float mu  = s * (1.f/Cc);
    float var = s2 * (1.f/Cc) - mu*mu;
    float inv = rsqrtf(var + 1e-5f);

    __nv_bfloat16* orow = out + (size_t)warp * Cc;
#pragma unroll
    for (int t = 0; t < 6; t++) {
        int c = lane + 32*t;
        orow[c] = __float2bfloat16((v[t]-mu)*inv*gamma[c] + beta[c]);
    }
}

// ---------- shared MMA helpers ----------
__device__ __forceinline__ void ldsm4(uint32_t f[4], uint32_t addr) {
    asm volatile("ldmatrix.sync.aligned.m8n8.x4.shared.b16 {%0,%1,%2,%3}, [%4];"
        : "=r"(f[0]), "=r"(f[1]), "=r"(f[2]), "=r"(f[3]) : "r"(addr));
}
__device__ __forceinline__ void ldsm4t(uint32_t f[4], uint32_t addr) {
    asm volatile("ldmatrix.sync.aligned.m8n8.x4.trans.shared.b16 {%0,%1,%2,%3}, [%4];"
        : "=r"(f[0]), "=r"(f[1]), "=r"(f[2]), "=r"(f[3]) : "r"(addr));
}
__device__ __forceinline__ void mma_bf16(float c[4], const uint32_t a[4],
                                         uint32_t b0, uint32_t b1) {
    asm volatile("mma.sync.aligned.m16n8k16.row.col.f32.bf16.bf16.f32 "
        "{%0,%1,%2,%3}, {%4,%5,%6,%7}, {%8,%9}, {%0,%1,%2,%3};"
        : "+f"(c[0]), "+f"(c[1]), "+f"(c[2]), "+f"(c[3])
        : "r"(a[0]), "r"(a[1]), "r"(a[2]), "r"(a[3]), "r"(b0), "r"(b1));
}
__device__ __forceinline__ void cp16(uint32_t dst, const void* src) {
    asm volatile("cp.async.cg.shared.global [%0], [%1], 16;" :: "r"(dst), "l"(src));
}

// ============================================================
// BF16 tensor-core NT-GEMM with ldmatrix + cp.async 2-stage
// (unchanged from R6)
// ============================================================
__device__ __forceinline__ uint32_t swzoff(int r, int c8) {
    return (uint32_t)(r*32 + ((c8 ^ ((r>>1)&3)) << 3));
}

template<int EPI>
__global__ __launch_bounds__(256) void k_gemm_bf16(
        const __nv_bfloat16* __restrict__ A,
        const __nv_bfloat16* __restrict__ W,
        const float* __restrict__ bias,
        void* __restrict__ outv,
        const float* __restrict__ resid,
        int Ntot)
{
    __shared__ __align__(16) __nv_bfloat16 As[2][64*32];
    __shared__ __align__(16) __nv_bfloat16 Bs[2][192*32];
    int tid = threadIdx.x, lane = tid & 31, w = tid >> 5;
    int wm = (w & 1) * 32, wn = (w >> 1) * 48;
    int m0 = blockIdx.x * 64, n0 = blockIdx.y * 192;

    uint32_t sA = (uint32_t)__cvta_generic_to_shared(&As[0][0]);
    uint32_t sB = (uint32_t)__cvta_generic_to_shared(&Bs[0][0]);
    const uint32_t stgA = 64*32*2, stgB = 192*32*2;

    int arow = tid >> 2, aslot = tid & 3;
    const __nv_bfloat16* asrc = A + (size_t)(m0 + arow)*192 + aslot*8;
    uint32_t adst = sA + 2*swzoff(arow, aslot);
    const __nv_bfloat16* bsrc[3];
    uint32_t bdst[3];
#pragma unroll
    for (int p = 0; p < 3; p++) {
        int i = tid + p*256;
        int br = i >> 2, bs = i & 3;
        bsrc[p] = W + (size_t)(n0 + br)*192 + bs*8;
        bdst[p] = sB + 2*swzoff(br, bs);
    }

    float acc[2][6][4];
#pragma unroll
    for (int mt = 0; mt < 2; mt++)
#pragma unroll
        for (int nt = 0; nt < 6; nt++)
#pragma unroll
            for (int i = 0; i < 4; i++) acc[mt][nt][i] = 0.f;

    cp16(adst, asrc);
#pragma unroll
    for (int p = 0; p < 3; p++) cp16(bdst[p], bsrc[p]);
    asm volatile("cp.async.commit_group;");

    for (int it = 0; it < 6; it++) {
        asm volatile("cp.async.wait_group 0;");
        __syncthreads();
        if (it + 1 < 6) {
            int st = (it + 1) & 1;
            int koff = (it + 1) * 32;
            cp16(adst + st*stgA, asrc + koff);
#pragma unroll
            for (int p = 0; p < 3; p++) cp16(bdst[p] + st*stgB, bsrc[p] + koff);
            asm volatile("cp.async.commit_group;");
        }
        uint32_t baseA = sA + (it & 1)*stgA;
        uint32_t baseB = sB + (it & 1)*stgB;
#pragma unroll
        for (int kk8 = 0; kk8 < 4; kk8 += 2) {
            uint32_t af[2][4];
#pragma unroll
            for (int mh = 0; mh < 2; mh++) {
                int row = wm + mh*16 + (lane & 15);
                int c8  = kk8 + (lane >> 4);
                ldsm4(af[mh], baseA + 2*swzoff(row, c8));
            }
            uint32_t bfr[3][4];
#pragma unroll
            for (int nh = 0; nh < 3; nh++) {
                int row = wn + nh*16 + ((lane >> 4) << 3) + (lane & 7);
                int c8  = kk8 + ((lane >> 3) & 1);
                ldsm4(bfr[nh], baseB + 2*swzoff(row, c8));
            }
#pragma unroll
            for (int mt = 0; mt < 2; mt++)
#pragma unroll
                for (int nt = 0; nt < 6; nt++)
                    mma_bf16(acc[mt][nt], af[mt],
                             bfr[nt >> 1][(nt & 1)*2], bfr[nt >> 1][(nt & 1)*2 + 1]);
        }
        __syncthreads();
    }

    int r = lane >> 2, q2 = (lane & 3) * 2;
    float bb[6][2];
#pragma unroll
    for (int nt = 0; nt < 6; nt++) {
        bb[nt][0] = bias[n0 + wn + nt*8 + q2];
        bb[nt][1] = bias[n0 + wn + nt*8 + q2 + 1];
    }

#pragma unroll
    for (int mt = 0; mt < 2; mt++)
#pragma unroll
    for (int half = 0; half < 2; half++) {
        int m = m0 + wm + mt*16 + r + half*8;
        if (EPI == 0) {
            __nv_bfloat16* orow = (__nv_bfloat16*)outv + (size_t)m*Ntot + n0 + wn;
#pragma unroll
            for (int nt = 0; nt < 6; nt++) {
                float x0 = acc[mt][nt][half*2+0] + bb[nt][0];
                float x1 = acc[mt][nt][half*2+1] + bb[nt][1];
                *(__nv_bfloat162*)(orow + nt*8 + q2) = __floats2bfloat162_rn(x0, x1);
            }
        } else if (EPI == 1) {
            int win = m / NN, n = m % NN;
            int bI = win >> 6, wr = win & 63;
            int wh = wr >> 3, ww = wr & 7;
            int hs = wh*WSz + n/WSz;
            int ws = ww*WSz + n%WSz;
            int dh = (hs + SHIFT) % Hdim;
            int dw = (ws + SHIFT) % Wdim;
            __nv_bfloat16* orow = (__nv_bfloat16*)outv +
                ((size_t)bI*(Hdim*Wdim) + dh*Wdim + dw)*Cc + n0 + wn;
#pragma unroll
            for (int nt = 0; nt < 6; nt++) {
                float x0 = acc[mt][nt][half*2+0] + bb[nt][0];
                float x1 = acc[mt][nt][half*2+1] + bb[nt][1];
                *(__nv_bfloat162*)(orow + nt*8 + q2) = __floats2bfloat162_rn(x0, x1);
            }
        } else {
            float* orow = (float*)outv + (size_t)m*Cc + n0 + wn;
            const float* rrow = resid + (size_t)m*Cc + n0 + wn;
#pragma unroll
            for (int nt = 0; nt < 6; nt++) {
                float x0 = acc[mt][nt][half*2+0] + bb[nt][0];
                float x1 = acc[mt][nt][half*2+1] + bb[nt][1];
                x0 = 0.5f*x0*(1.f + erff(x0*0.70710678118654752f));
                x1 = 0.5f*x1*(1.f + erff(x1*0.70710678118654752f));
                x0 += rrow[nt*8 + q2];
                x1 += rrow[nt*8 + q2 + 1];
                *(float2*)(orow + nt*8 + q2) = make_float2(x0, x1);
            }
        }
    }
}

// ============================================================
// Kernel 3: MMA windowed attention. Block = (window, head),
// 128 threads (4 warps). Pad 49 -> 64 with zeros.
// QK packed in one 128B-row swizzled tile (conflict-free ldsm).
// ============================================================
__global__ __launch_bounds__(128) void k_attn_mma(
        const __nv_bfloat16* __restrict__ qkv,
        const float* __restrict__ biasH,
        const float* __restrict__ mask,
        __nv_bfloat16* __restrict__ ctx)
{
    int win = blockIdx.x, hh = blockIdx.y;
    int tid = threadIdx.x, lane = tid & 31, w = tid >> 5;

    __shared__ __align__(16) __nv_bfloat16 QKs[64*64];  // Q c8 0-3, K c8 4-7
    __shared__ __align__(16) __nv_bfloat16 Vs [64*32];
    __shared__ __align__(16) __nv_bfloat16 Ps [64*64];
    __shared__ float Ss[64][66];
    __shared__ float rinv[64];

    const __nv_bfloat16* base = qkv + (size_t)win*NN*576 + hh*HD;

    // load Q,K (packed) with zero padding; swizzle c8 ^= r&7
    for (int idx = tid; idx < 512; idx += 128) {
        int r = idx >> 3, c8 = idx & 7;
        float4 val = make_float4(0.f,0.f,0.f,0.f);
        if (r < NN)
            val = *(const float4*)(base + (size_t)r*576 + ((c8 >> 2) ? 192 : 0) + (c8 & 3)*8);
        *(float4*)(QKs + r*64 + ((c8 ^ (r & 7)) << 3)) = val;
    }
    // load V (zero padded); swizzle c8 ^= r&3
    for (int idx = tid; idx < 256; idx += 128) {
        int r = idx >> 2, c8 = idx & 3;
        float4 val = make_float4(0.f,0.f,0.f,0.f);
        if (r < NN)
            val = *(const float4*)(base + (size_t)r*576 + 384 + c8*8);
        *(float4*)(Vs + r*32 + ((c8 ^ (r & 3)) << 3)) = val;
    }
    // zero P pad cols (chunks 6,7 = cols 48..63); col 48 rewritten by softmax
    {
        int r = tid >> 1, c8 = 6 + (tid & 1);
        *(float4*)(Ps + r*64 + ((c8 ^ (r & 7)) << 3)) = make_float4(0.f,0.f,0.f,0.f);
    }
    __syncthreads();

    uint32_t sQK = (uint32_t)__cvta_generic_to_shared(QKs);
    uint32_t sV  = (uint32_t)__cvta_generic_to_shared(Vs);
    uint32_t sP  = (uint32_t)__cvta_generic_to_shared(Ps);

    // ---- S = Q @ K^T (each warp: rows w*16..+15, all 64 cols) ----
    {
        float sacc[8][4];
#pragma unroll
        for (int nt = 0; nt < 8; nt++)
#pragma unroll
            for (int i = 0; i < 4; i++) sacc[nt][i] = 0.f;

#pragma unroll
        for (int kk = 0; kk < 2; kk++) {
            uint32_t a[4];
            {
                int j = lane >> 3;
                int row = w*16 + (j & 1)*8 + (lane & 7);
                int c8  = kk*2 + (j >> 1);
                ldsm4(a, sQK + 2*(row*64 + ((c8 ^ (row & 7)) << 3)));
            }
            uint32_t b[4][4];
#pragma unroll
            for (int t = 0; t < 4; t++) {
                int row = t*16 + ((lane >> 4) << 3) + (lane & 7);
                int c8  = 4 + kk*2 + ((lane >> 3) & 1);
                ldsm4(b[t], sQK + 2*(row*64 + ((c8 ^ (row & 7)) << 3)));
            }
#pragma unroll
            for (int nt = 0; nt < 8; nt++)
                mma_bf16(sacc[nt], a, b[nt >> 1][(nt & 1)*2], b[nt >> 1][(nt & 1)*2 + 1]);
        }
        int r = w*16 + (lane >> 2), q2 = (lane & 3)*2;
#pragma unroll
        for (int nt = 0; nt < 8; nt++) {
            Ss[r  ][nt*8 + q2]     = sacc[nt][0];
            Ss[r  ][nt*8 + q2 + 1] = sacc[nt][1];
            Ss[r+8][nt*8 + q2]     = sacc[nt][2];
            Ss[r+8][nt*8 + q2 + 1] = sacc[nt][3];
        }
    }
    __syncthreads();

    // ---- softmax: 2 threads per row, rows 0..63 ----
    {
        int r = tid >> 1, hf = tid & 1;
        int lo = hf ? 25 : 0, hi = hf ? NN : 25;
        const float* bh = biasH + hh*(NN*NN) + r*NN;
        const float* mk = mask + (size_t)(win & 63)*(NN*NN) + r*NN;
        float mx = -1e30f;
        for (int m = lo; m < hi; m++) {
            float v = Ss[r][m] * QSCALE;
            if (r < NN) v += bh[m] + mk[m];
            Ss[r][m] = v;
            mx = fmaxf(mx, v);
        }
        mx = fmaxf(mx, __shfl_xor_sync(0xffffffffu, mx, 1));
        float sum = 0.f;
        for (int m = lo; m < hi; m++) {
            float e = __expf(Ss[r][m] - mx);
            sum += e;
            Ps[r*64 + (((m >> 3) ^ (r & 7)) << 3) + (m & 7)] = __float2bfloat16(e);
        }
        sum += __shfl_xor_sync(0xffffffffu, sum, 1);
        if (hf == 0) rinv[r] = 1.f / sum;
    }
    __syncthreads();

    // ---- O = P @ V (each warp: rows w*16..+15, 32 cols) ----
    {
        float oacc[4][4];
#pragma unroll
        for (int nt = 0; nt < 4; nt++)
#pragma unroll
            for (int i = 0; i < 4; i++) oacc[nt][i] = 0.f;

#pragma unroll
        for (int kk = 0; kk < 4; kk++) {
            uint32_t a[4];
            {
                int j = lane >> 3;
                int row = w*16 + (j & 1)*8 + (lane & 7);
                int c8  = kk*2 + (j >> 1);
                ldsm4(a, sP + 2*(row*64 + ((c8 ^ (row & 7)) << 3)));
            }
            uint32_t b[2][4];
#pragma unroll
            for (int t = 0; t < 2; t++) {
                int j = lane >> 3;
                int row = kk*16 + (j & 1)*8 + (lane & 7);   // seq (k) rows
                int c8  = t*2 + (j >> 1);                   // d chunks
                ldsm4t(b[t], sV + 2*(row*32 + ((c8 ^ (row & 3)) << 3)));
            }
#pragma unroll
            for (int nt = 0; nt < 4; nt++)
                mma_bf16(oacc[nt], a, b[nt >> 1][(nt & 1)*2], b[nt >> 1][(nt & 1)*2 + 1]);
        }

        int r0 = w*16 + (lane >> 2), q2 = (lane & 3)*2;
        float ri0 = rinv[r0], ri1 = rinv[r0 + 8];
        __nv_bfloat16* c0 = ctx + ((size_t)win*NN + r0)*Cc + hh*HD;
        __nv_bfloat16* c1 = c0 + (size_t)8*Cc;
#pragma unroll
        for (int nt = 0; nt < 4; nt++) {
            if (r0 < NN)
                *(__nv_bfloat162*)(c0 + nt*8 + q2) =
                    __floats2bfloat162_rn(oacc[nt][0]*ri0, oacc[nt][1]*ri0);
            if (r0 + 8 < NN)
                *(__nv_bfloat162*)(c1 + nt*8 + q2) =
                    __floats2bfloat162_rn(oacc[nt][2]*ri1, oacc[nt][3]*ri1);
        }
    }
}

// ============================================================
extern "C" void kernel_launch(void* const* d_in, const int* in_sizes, int n_in,
                              void* d_out, int out_size)
{
    const float* inputs = (const float*)d_in[0];
    const float* mask   = (const float*)d_in[1];
    const float* n1g    = (const float*)d_in[2];
    const float* n1b    = (const float*)d_in[3];
    const float* qkv_w  = (const float*)d_in[4];
    const float* qkv_b  = (const float*)d_in[5];
    const float* table  = (const float*)d_in[6];
    const int*   rpi    = (const int*)  d_in[7];
    const float* proj_w = (const float*)d_in[8];
    const float* proj_b = (const float*)d_in[9];
    const float* lin_w  = (const float*)d_in[10];
    const float* lin_b  = (const float*)d_in[11];
    float* out = (float*)d_out;

    __nv_bfloat16 *p_win, *p_qkv, *p_ctx, *p_attn, *p_wq, *p_wp, *p_wl;
    float* p_biasH;
    cudaGetSymbolAddress((void**)&p_win,  g_win);
    cudaGetSymbolAddress((void**)&p_qkv,  g_qkv);
    cudaGetSymbolAddress((void**)&p_ctx,  g_ctx);
    cudaGetSymbolAddress((void**)&p_attn, g_attn);
    cudaGetSymbolAddress((void**)&p_wq,   g_wq);
    cudaGetSymbolAddress((void**)&p_wp,   g_wp);
    cudaGetSymbolAddress((void**)&p_wl,   g_wl);
    cudaGetSymbolAddress((void**)&p_biasH, g_biasH);

    // 0. weight conversion + bias gather
    k_cvt<<<(576*192 + 255)/256, 256>>>(qkv_w, proj_w, lin_w, table, rpi);

    // 1. LN + shift + partition (bf16 out)
    k_ln_part<<<(TOK*32 + 255)/256, 256>>>(inputs, n1g, n1b, p_win);

    // 2. QKV GEMM -> bf16
    {
        dim3 grid(TOK/64, 3);
        k_gemm_bf16<0><<<grid, 256>>>(p_win, p_wq, qkv_b, p_qkv, nullptr, 3*Cc);
    }
    // 3. MMA attention
    {
        dim3 grid(BWIN, NHd);
        k_attn_mma<<<grid, 128>>>(p_qkv, p_biasH, mask, p_ctx);
    }
    // 4. Proj GEMM + window reverse scatter -> bf16
    {
        dim3 grid(TOK/64, 1);
        k_gemm_bf16<1><<<grid, 256>>>(p_ctx, p_wp, proj_b, p_attn, nullptr, Cc);
    }
    // 5. MLP GEMM + exact gelu + residual -> fp32 out
    {
        dim3 grid(TOK/64, 1);
        k_gemm_bf16<2><<<grid, 256>>>(p_attn, p_wl, lin_b, out, inputs, Cc);
    }
}

// round 9
// speedup vs baseline: 5.5744x; 1.4448x over previous
#include <cuda_runtime.h>
#include <cuda_bf16.h>
#include <math.h>
#include <stdint.h>

#define Bsz   32
#define Hdim  56
#define Wdim  56
#define Cc    192
#define WSz   7
#define SHIFT 3
#define NHd   6
#define HD    32
#define NN    49
#define NWIN  64
#define BWIN  (Bsz*NWIN)    // 2048
#define TOK   (BWIN*NN)     // 100352
#define QSCALE 0.17677669529663689f

// ---- scratch (device globals; no allocation allowed) ----
__device__ __nv_bfloat16 g_win [(size_t)TOK*Cc];
__device__ __nv_bfloat16 g_qkv [(size_t)TOK*3*Cc];
__device__ __nv_bfloat16 g_ctx [(size_t)TOK*Cc];
__device__ __nv_bfloat16 g_attn[(size_t)TOK*Cc];
__device__ __nv_bfloat16 g_wq  [576*192];
__device__ __nv_bfloat16 g_wp  [192*192];
__device__ __nv_bfloat16 g_wl  [192*192];
// combined bias+mask table, padded 64x64 per (head, nw); pad = -1e30
__device__ float         g_tbl [6*64*64*64];

// ============================================================
// Kernel 0: weights fp32->bf16 + combined bias/mask table
// ============================================================
__global__ void k_cvt(const float* __restrict__ wq,
                      const float* __restrict__ wp,
                      const float* __restrict__ wl,
                      const float* __restrict__ table,
                      const int*   __restrict__ rpi,
                      const float* __restrict__ mask)
{
    int i = blockIdx.x * blockDim.x + threadIdx.x;
    if (i < 576*192) g_wq[i] = __float2bfloat16(wq[i]);
    if (i < 192*192) {
        g_wp[i] = __float2bfloat16(wp[i]);
        g_wl[i] = __float2bfloat16(wl[i]);
    }
    if (i < 6*64*64*64) {
        int c  = i & 63;
        int r  = (i >> 6) & 63;
        int nw = (i >> 12) & 63;
        int h  = i >> 18;
        float v = -1e30f;
        if (r < NN && c < NN)
            v = table[rpi[r*NN + c]*NHd + h] + mask[(size_t)nw*NN*NN + r*NN + c];
        g_tbl[i] = v;
    }
}

// ============================================================
// Kernel 1: LayerNorm + cyclic shift(-3,-3) + window partition
// ============================================================
__global__ void k_ln_part(const float* __restrict__ x,
                          const float* __restrict__ gamma,
                          const float* __restrict__ beta,
                          __nv_bfloat16* __restrict__ out)
{
    int warp = (blockIdx.x * blockDim.x + threadIdx.x) >> 5;
    int lane = threadIdx.x & 31;
    if (warp >= TOK) return;
    int win = warp / NN, n = warp % NN;
    int bI = win >> 6, wr = win & 63;
    int wh = wr >> 3, ww = wr & 7;
    int hs = wh * WSz + n / WSz;
    int ws = ww * WSz + n % WSz;
    int h = (hs + SHIFT) % Hdim;
    int w = (ws + SHIFT) % Wdim;
    const float* row = x + ((size_t)bI * (Hdim*Wdim) + h * Wdim + w) * Cc;

    float v[6], s = 0.f, s2 = 0.f;
#pragma unroll
    for (int t = 0; t < 6; t++) {
        v[t] = row[lane + 32*t];
        s  += v[t];
        s2 += v[t]*v[t];
    }
#pragma unroll
    for (int o = 16; o; o >>= 1) {
        s  += __shfl_xor_sync(0xffffffffu, s,  o);
        s2 += __shfl_xor_sync(0xffffffffu, s2, o);
    }
    float mu  = s * (1.f/Cc);
    float var = s2 * (1.f/Cc) - mu*mu;
    float inv = rsqrtf(var + 1e-5f);

    __nv_bfloat16* orow = out + (size_t)warp * Cc;
#pragma unroll
    for (int t = 0; t < 6; t++) {
        int c = lane + 32*t;
        orow[c] = __float2bfloat16((v[t]-mu)*inv*gamma[c] + beta[c]);
    }
}

// ---------- shared MMA helpers ----------
__device__ __forceinline__ void ldsm4(uint32_t f[4], uint32_t addr) {
    asm volatile("ldmatrix.sync.aligned.m8n8.x4.shared.b16 {%0,%1,%2,%3}, [%4];"
        : "=r"(f[0]), "=r"(f[1]), "=r"(f[2]), "=r"(f[3]) : "r"(addr));
}
__device__ __forceinline__ void ldsm4t(uint32_t f[4], uint32_t addr) {
    asm volatile("ldmatrix.sync.aligned.m8n8.x4.trans.shared.b16 {%0,%1,%2,%3}, [%4];"
        : "=r"(f[0]), "=r"(f[1]), "=r"(f[2]), "=r"(f[3]) : "r"(addr));
}
__device__ __forceinline__ void mma_bf16(float c[4], const uint32_t a[4],
                                         uint32_t b0, uint32_t b1) {
    asm volatile("mma.sync.aligned.m16n8k16.row.col.f32.bf16.bf16.f32 "
        "{%0,%1,%2,%3}, {%4,%5,%6,%7}, {%8,%9}, {%0,%1,%2,%3};"
        : "+f"(c[0]), "+f"(c[1]), "+f"(c[2]), "+f"(c[3])
        : "r"(a[0]), "r"(a[1]), "r"(a[2]), "r"(a[3]), "r"(b0), "r"(b1));
}
__device__ __forceinline__ void cp16(uint32_t dst, const void* src) {
    asm volatile("cp.async.cg.shared.global [%0], [%1], 16;" :: "r"(dst), "l"(src));
}

// ============================================================
// BF16 tensor-core NT-GEMM with ldmatrix + cp.async 2-stage
// (unchanged — verified in R6/R7)
// ============================================================
__device__ __forceinline__ uint32_t swzoff(int r, int c8) {
    return (uint32_t)(r*32 + ((c8 ^ ((r>>1)&3)) << 3));
}

template<int EPI>
__global__ __launch_bounds__(256) void k_gemm_bf16(
        const __nv_bfloat16* __restrict__ A,
        const __nv_bfloat16* __restrict__ W,
        const float* __restrict__ bias,
        void* __restrict__ outv,
        const float* __restrict__ resid,
        int Ntot)
{
    __shared__ __align__(16) __nv_bfloat16 As[2][64*32];
    __shared__ __align__(16) __nv_bfloat16 Bs[2][192*32];
    int tid = threadIdx.x, lane = tid & 31, w = tid >> 5;
    int wm = (w & 1) * 32, wn = (w >> 1) * 48;
    int m0 = blockIdx.x * 64, n0 = blockIdx.y * 192;

    uint32_t sA = (uint32_t)__cvta_generic_to_shared(&As[0][0]);
    uint32_t sB = (uint32_t)__cvta_generic_to_shared(&Bs[0][0]);
    const uint32_t stgA = 64*32*2, stgB = 192*32*2;

    int arow = tid >> 2, aslot = tid & 3;
    const __nv_bfloat16* asrc = A + (size_t)(m0 + arow)*192 + aslot*8;
    uint32_t adst = sA + 2*swzoff(arow, aslot);
    const __nv_bfloat16* bsrc[3];
    uint32_t bdst[3];
#pragma unroll
    for (int p = 0; p < 3; p++) {
        int i = tid + p*256;
        int br = i >> 2, bs = i & 3;
        bsrc[p] = W + (size_t)(n0 + br)*192 + bs*8;
        bdst[p] = sB + 2*swzoff(br, bs);
    }

    float acc[2][6][4];
#pragma unroll
    for (int mt = 0; mt < 2; mt++)
#pragma unroll
        for (int nt = 0; nt < 6; nt++)
#pragma unroll
            for (int i = 0; i < 4; i++) acc[mt][nt][i] = 0.f;

    cp16(adst, asrc);
#pragma unroll
    for (int p = 0; p < 3; p++) cp16(bdst[p], bsrc[p]);
    asm volatile("cp.async.commit_group;");

    for (int it = 0; it < 6; it++) {
        asm volatile("cp.async.wait_group 0;");
        __syncthreads();
        if (it + 1 < 6) {
            int st = (it + 1) & 1;
            int koff = (it + 1) * 32;
            cp16(adst + st*stgA, asrc + koff);
#pragma unroll
            for (int p = 0; p < 3; p++) cp16(bdst[p] + st*stgB, bsrc[p] + koff);
            asm volatile("cp.async.commit_group;");
        }
        uint32_t baseA = sA + (it & 1)*stgA;
        uint32_t baseB = sB + (it & 1)*stgB;
#pragma unroll
        for (int kk8 = 0; kk8 < 4; kk8 += 2) {
            uint32_t af[2][4];
#pragma unroll
            for (int mh = 0; mh < 2; mh++) {
                int row = wm + mh*16 + (lane & 15);
                int c8  = kk8 + (lane >> 4);
                ldsm4(af[mh], baseA + 2*swzoff(row, c8));
            }
            uint32_t bfr[3][4];
#pragma unroll
            for (int nh = 0; nh < 3; nh++) {
                int row = wn + nh*16 + ((lane >> 4) << 3) + (lane & 7);
                int c8  = kk8 + ((lane >> 3) & 1);
                ldsm4(bfr[nh], baseB + 2*swzoff(row, c8));
            }
#pragma unroll
            for (int mt = 0; mt < 2; mt++)
#pragma unroll
                for (int nt = 0; nt < 6; nt++)
                    mma_bf16(acc[mt][nt], af[mt],
                             bfr[nt >> 1][(nt & 1)*2], bfr[nt >> 1][(nt & 1)*2 + 1]);
        }
        __syncthreads();
    }

    int r = lane >> 2, q2 = (lane & 3) * 2;
    float bb[6][2];
#pragma unroll
    for (int nt = 0; nt < 6; nt++) {
        bb[nt][0] = bias[n0 + wn + nt*8 + q2];
        bb[nt][1] = bias[n0 + wn + nt*8 + q2 + 1];
    }

#pragma unroll
    for (int mt = 0; mt < 2; mt++)
#pragma unroll
    for (int half = 0; half < 2; half++) {
        int m = m0 + wm + mt*16 + r + half*8;
        if (EPI == 0) {
            __nv_bfloat16* orow = (__nv_bfloat16*)outv + (size_t)m*Ntot + n0 + wn;
#pragma unroll
            for (int nt = 0; nt < 6; nt++) {
                float x0 = acc[mt][nt][half*2+0] + bb[nt][0];
                float x1 = acc[mt][nt][half*2+1] + bb[nt][1];
                *(__nv_bfloat162*)(orow + nt*8 + q2) = __floats2bfloat162_rn(x0, x1);
            }
        } else if (EPI == 1) {
            int win = m / NN, n = m % NN;
            int bI = win >> 6, wr = win & 63;
            int wh = wr >> 3, ww = wr & 7;
            int hs = wh*WSz + n/WSz;
            int ws = ww*WSz + n%WSz;
            int dh = (hs + SHIFT) % Hdim;
            int dw = (ws + SHIFT) % Wdim;
            __nv_bfloat16* orow = (__nv_bfloat16*)outv +
                ((size_t)bI*(Hdim*Wdim) + dh*Wdim + dw)*Cc + n0 + wn;
#pragma unroll
            for (int nt = 0; nt < 6; nt++) {
                float x0 = acc[mt][nt][half*2+0] + bb[nt][0];
                float x1 = acc[mt][nt][half*2+1] + bb[nt][1];
                *(__nv_bfloat162*)(orow + nt*8 + q2) = __floats2bfloat162_rn(x0, x1);
            }
        } else {
            float* orow = (float*)outv + (size_t)m*Cc + n0 + wn;
            const float* rrow = resid + (size_t)m*Cc + n0 + wn;
#pragma unroll
            for (int nt = 0; nt < 6; nt++) {
                float x0 = acc[mt][nt][half*2+0] + bb[nt][0];
                float x1 = acc[mt][nt][half*2+1] + bb[nt][1];
                x0 = 0.5f*x0*(1.f + erff(x0*0.70710678118654752f));
                x1 = 0.5f*x1*(1.f + erff(x1*0.70710678118654752f));
                x0 += rrow[nt*8 + q2];
                x1 += rrow[nt*8 + q2 + 1];
                *(float2*)(orow + nt*8 + q2) = make_float2(x0, x1);
            }
        }
    }
}

// ============================================================
// Kernel 3: MMA attention, softmax fully in registers.
// Block = (window, head), 128 threads (4 warps).
// Warp w owns S rows [16w,16w+16) x all 64 cols -> P stays in regs
// as the PV A-operand. Only QK + V smem tiles remain (12KB).
// ============================================================
__global__ __launch_bounds__(128) void k_attn_mma(
        const __nv_bfloat16* __restrict__ qkv,
        const float* __restrict__ tbl,
        __nv_bfloat16* __restrict__ ctx)
{
    int win = blockIdx.x, hh = blockIdx.y;
    int tid = threadIdx.x, lane = tid & 31, w = tid >> 5;

    __shared__ __align__(16) __nv_bfloat16 QKs[64*64];  // Q c8 0-3, K c8 4-7
    __shared__ __align__(16) __nv_bfloat16 Vs [64*32];

    const __nv_bfloat16* base = qkv + (size_t)win*NN*576 + hh*HD;

    // load Q,K packed, zero-padded; swizzle c8 ^= r&7
    for (int idx = tid; idx < 512; idx += 128) {
        int r = idx >> 3, c8 = idx & 7;
        float4 val = make_float4(0.f,0.f,0.f,0.f);
        if (r < NN)
            val = *(const float4*)(base + (size_t)r*576 + ((c8 >> 2) ? 192 : 0) + (c8 & 3)*8);
        *(float4*)(QKs + r*64 + ((c8 ^ (r & 7)) << 3)) = val;
    }
    // load V zero-padded; swizzle c8 ^= r&3
    for (int idx = tid; idx < 256; idx += 128) {
        int r = idx >> 2, c8 = idx & 3;
        float4 val = make_float4(0.f,0.f,0.f,0.f);
        if (r < NN)
            val = *(const float4*)(base + (size_t)r*576 + 384 + c8*8);
        *(float4*)(Vs + r*32 + ((c8 ^ (r & 3)) << 3)) = val;
    }
    __syncthreads();

    uint32_t sQK = (uint32_t)__cvta_generic_to_shared(QKs);
    uint32_t sV  = (uint32_t)__cvta_generic_to_shared(Vs);

    // ---- S = Q @ K^T : warp rows [16w,16w+16), cols 0..63 ----
    float sacc[8][4];
#pragma unroll
    for (int nt = 0; nt < 8; nt++)
#pragma unroll
        for (int i = 0; i < 4; i++) sacc[nt][i] = 0.f;

#pragma unroll
    for (int kk = 0; kk < 2; kk++) {
        uint32_t a[4];
        {
            int j = lane >> 3;
            int row = w*16 + (j & 1)*8 + (lane & 7);
            int c8  = kk*2 + (j >> 1);
            ldsm4(a, sQK + 2*(row*64 + ((c8 ^ (row & 7)) << 3)));
        }
        uint32_t b[4][4];
#pragma unroll
        for (int t = 0; t < 4; t++) {
            int row = t*16 + ((lane >> 4) << 3) + (lane & 7);
            int c8  = 4 + kk*2 + ((lane >> 3) & 1);
            ldsm4(b[t], sQK + 2*(row*64 + ((c8 ^ (row & 7)) << 3)));
        }
#pragma unroll
        for (int nt = 0; nt < 8; nt++)
            mma_bf16(sacc[nt], a, b[nt >> 1][(nt & 1)*2], b[nt >> 1][(nt & 1)*2 + 1]);
    }

    // ---- softmax in registers (quad shfl reduce) ----
    int r = lane >> 2, q2 = (lane & 3)*2;
    int row0 = w*16 + r;
    const float* t0 = tbl + (((size_t)hh*64 + (win & 63))*64 + row0)*64;
    const float* t1 = t0 + 8*64;

    float v0[16], v1[16];
    float mx0 = -1e30f, mx1 = -1e30f;
#pragma unroll
    for (int nt = 0; nt < 8; nt++) {
        float2 b0 = *(const float2*)(t0 + nt*8 + q2);
        float2 b1 = *(const float2*)(t1 + nt*8 + q2);
        v0[2*nt]   = fmaf(sacc[nt][0], QSCALE, b0.x);
        v0[2*nt+1] = fmaf(sacc[nt][1], QSCALE, b0.y);
        v1[2*nt]   = fmaf(sacc[nt][2], QSCALE, b1.x);
        v1[2*nt+1] = fmaf(sacc[nt][3], QSCALE, b1.y);
        mx0 = fmaxf(mx0, fmaxf(v0[2*nt], v0[2*nt+1]));
        mx1 = fmaxf(mx1, fmaxf(v1[2*nt], v1[2*nt+1]));
    }
    mx0 = fmaxf(mx0, __shfl_xor_sync(0xffffffffu, mx0, 1));
    mx0 = fmaxf(mx0, __shfl_xor_sync(0xffffffffu, mx0, 2));
    mx1 = fmaxf(mx1, __shfl_xor_sync(0xffffffffu, mx1, 1));
    mx1 = fmaxf(mx1, __shfl_xor_sync(0xffffffffu, mx1, 2));

    uint32_t pk0[8], pk1[8];
    float sum0 = 0.f, sum1 = 0.f;
#pragma unroll
    for (int nt = 0; nt < 8; nt++) {
        float e0a = __expf(v0[2*nt]   - mx0);
        float e0b = __expf(v0[2*nt+1] - mx0);
        float e1a = __expf(v1[2*nt]   - mx1);
        float e1b = __expf(v1[2*nt+1] - mx1);
        sum0 += e0a + e0b;
        sum1 += e1a + e1b;
        __nv_bfloat162 p0 = __floats2bfloat162_rn(e0a, e0b);
        __nv_bfloat162 p1 = __floats2bfloat162_rn(e1a, e1b);
        pk0[nt] = *(uint32_t*)&p0;
        pk1[nt] = *(uint32_t*)&p1;
    }
    sum0 += __shfl_xor_sync(0xffffffffu, sum0, 1);
    sum0 += __shfl_xor_sync(0xffffffffu, sum0, 2);
    sum1 += __shfl_xor_sync(0xffffffffu, sum1, 1);
    sum1 += __shfl_xor_sync(0xffffffffu, sum1, 2);
    float ri0 = 1.f / sum0, ri1 = 1.f / sum1;

    // ---- O = P @ V : A from registers, B = V via ldsm trans ----
    float oacc[4][4];
#pragma unroll
    for (int nt = 0; nt < 4; nt++)
#pragma unroll
        for (int i = 0; i < 4; i++) oacc[nt][i] = 0.f;

#pragma unroll
    for (int kk = 0; kk < 4; kk++) {
        uint32_t a[4] = { pk0[2*kk], pk1[2*kk], pk0[2*kk+1], pk1[2*kk+1] };
        uint32_t b[2][4];
#pragma unroll
        for (int t = 0; t < 2; t++) {
            int j = lane >> 3;
            int row = kk*16 + (j & 1)*8 + (lane & 7);   // seq (k) rows
            int c8  = t*2 + (j >> 1);                   // d chunks
            ldsm4t(b[t], sV + 2*(row*32 + ((c8 ^ (row & 3)) << 3)));
        }
#pragma unroll
        for (int nt = 0; nt < 4; nt++)
            mma_bf16(oacc[nt], a, b[nt >> 1][(nt & 1)*2], b[nt >> 1][(nt & 1)*2 + 1]);
    }

    __nv_bfloat16* c0 = ctx + ((size_t)win*NN + row0)*Cc + hh*HD;
    __nv_bfloat16* c1 = c0 + (size_t)8*Cc;
#pragma unroll
    for (int nt = 0; nt < 4; nt++) {
        if (row0 < NN)
            *(__nv_bfloat162*)(c0 + nt*8 + q2) =
                __floats2bfloat162_rn(oacc[nt][0]*ri0, oacc[nt][1]*ri0);
        if (row0 + 8 < NN)
            *(__nv_bfloat162*)(c1 + nt*8 + q2) =
                __floats2bfloat162_rn(oacc[nt][2]*ri1, oacc[nt][3]*ri1);
    }
}

// ============================================================
extern "C" void kernel_launch(void* const* d_in, const int* in_sizes, int n_in,
                              void* d_out, int out_size)
{
    const float* inputs = (const float*)d_in[0];
    const float* mask   = (const float*)d_in[1];
    const float* n1g    = (const float*)d_in[2];
    const float* n1b    = (const float*)d_in[3];
    const float* qkv_w  = (const float*)d_in[4];
    const float* qkv_b  = (const float*)d_in[5];
    const float* table  = (const float*)d_in[6];
    const int*   rpi    = (const int*)  d_in[7];
    const float* proj_w = (const float*)d_in[8];
    const float* proj_b = (const float*)d_in[9];
    const float* lin_w  = (const float*)d_in[10];
    const float* lin_b  = (const float*)d_in[11];
    float* out = (float*)d_out;

    __nv_bfloat16 *p_win, *p_qkv, *p_ctx, *p_attn, *p_wq, *p_wp, *p_wl;
    float* p_tbl;
    cudaGetSymbolAddress((void**)&p_win,  g_win);
    cudaGetSymbolAddress((void**)&p_qkv,  g_qkv);
    cudaGetSymbolAddress((void**)&p_ctx,  g_ctx);
    cudaGetSymbolAddress((void**)&p_attn, g_attn);
    cudaGetSymbolAddress((void**)&p_wq,   g_wq);
    cudaGetSymbolAddress((void**)&p_wp,   g_wp);
    cudaGetSymbolAddress((void**)&p_wl,   g_wl);
    cudaGetSymbolAddress((void**)&p_tbl,  g_tbl);

    // 0. weight conversion + combined bias/mask table
    k_cvt<<<(6*64*64*64 + 255)/256, 256>>>(qkv_w, proj_w, lin_w, table, rpi, mask);

    // 1. LN + shift + partition (bf16 out)
    k_ln_part<<<(TOK*32 + 255)/256, 256>>>(inputs, n1g, n1b, p_win);

    // 2. QKV GEMM -> bf16
    {
        dim3 grid(TOK/64, 3);
        k_gemm_bf16<0><<<grid, 256>>>(p_win, p_wq, qkv_b, p_qkv, nullptr, 3*Cc);
    }
    // 3. MMA attention (register softmax)
    {
        dim3 grid(BWIN, NHd);
        k_attn_mma<<<grid, 128>>>(p_qkv, p_tbl, p_ctx);
    }
    // 4. Proj GEMM + window reverse scatter -> bf16
    {
        dim3 grid(TOK/64, 1);
        k_gemm_bf16<1><<<grid, 256>>>(p_ctx, p_wp, proj_b, p_attn, nullptr, Cc);
    }
    // 5. MLP GEMM + exact gelu + residual -> fp32 out
    {
        dim3 grid(TOK/64, 1);
        k_gemm_bf16<2><<<grid, 256>>>(p_attn, p_wl, lin_b, out, inputs, Cc);
    }
}

// round 11
// speedup vs baseline: 5.6615x; 1.0156x over previous
#include <cuda_runtime.h>
#include <cuda_bf16.h>
#include <math.h>
#include <stdint.h>

#define Bsz   32
#define Hdim  56
#define Wdim  56
#define Cc    192
#define WSz   7
#define SHIFT 3
#define NHd   6
#define HD    32
#define NN    49
#define NWIN  64
#define BWIN  (Bsz*NWIN)    // 2048
#define TOK   (BWIN*NN)     // 100352
#define QSCALE 0.17677669529663689f

// ---- scratch (device globals; no allocation allowed) ----
__device__ __nv_bfloat16 g_win [(size_t)TOK*Cc];
__device__ __nv_bfloat16 g_qkv [(size_t)TOK*3*Cc];
__device__ __nv_bfloat16 g_attn[(size_t)TOK*Cc];
__device__ __nv_bfloat16 g_wq  [576*192];
__device__ __nv_bfloat16 g_wp  [192*192];
__device__ __nv_bfloat16 g_wl  [192*192];
// combined bias+mask table, padded 64x64 per (head, nw); pad = -1e30
__device__ float         g_tbl [6*64*64*64];

// ============================================================
// Kernel 0: weights fp32->bf16 + combined bias/mask table
// ============================================================
__global__ void k_cvt(const float* __restrict__ wq,
                      const float* __restrict__ wp,
                      const float* __restrict__ wl,
                      const float* __restrict__ table,
                      const int*   __restrict__ rpi,
                      const float* __restrict__ mask)
{
    int i = blockIdx.x * blockDim.x + threadIdx.x;
    if (i < 576*192) g_wq[i] = __float2bfloat16(wq[i]);
    if (i < 192*192) {
        g_wp[i] = __float2bfloat16(wp[i]);
        g_wl[i] = __float2bfloat16(wl[i]);
    }
    if (i < 6*64*64*64) {
        int c  = i & 63;
        int r  = (i >> 6) & 63;
        int nw = (i >> 12) & 63;
        int h  = i >> 18;
        float v = -1e30f;
        if (r < NN && c < NN)
            v = table[rpi[r*NN + c]*NHd + h] + mask[(size_t)nw*NN*NN + r*NN + c];
        g_tbl[i] = v;
    }
}

// ============================================================
// Kernel 1: LayerNorm + cyclic shift(-3,-3) + window partition
// ============================================================
__global__ void k_ln_part(const float* __restrict__ x,
                          const float* __restrict__ gamma,
                          const float* __restrict__ beta,
                          __nv_bfloat16* __restrict__ out)
{
    int warp = (blockIdx.x * blockDim.x + threadIdx.x) >> 5;
    int lane = threadIdx.x & 31;
    if (warp >= TOK) return;
    int win = warp / NN, n = warp % NN;
    int bI = win >> 6, wr = win & 63;
    int wh = wr >> 3, ww = wr & 7;
    int hs = wh * WSz + n / WSz;
    int ws = ww * WSz + n % WSz;
    int h = (hs + SHIFT) % Hdim;
    int w = (ws + SHIFT) % Wdim;
    const float* row = x + ((size_t)bI * (Hdim*Wdim) + h * Wdim + w) * Cc;

    float v[6], s = 0.f, s2 = 0.f;
#pragma unroll
    for (int t = 0; t < 6; t++) {
        v[t] = row[lane + 32*t];
        s  += v[t];
        s2 += v[t]*v[t];
    }
#pragma unroll
    for (int o = 16; o; o >>= 1) {
        s  += __shfl_xor_sync(0xffffffffu, s,  o);
        s2 += __shfl_xor_sync(0xffffffffu, s2, o);
    }
    float mu  = s * (1.f/Cc);
    float var = s2 * (1.f/Cc) - mu*mu;
    float inv = rsqrtf(var + 1e-5f);

    __nv_bfloat16* orow = out + (size_t)warp * Cc;
#pragma unroll
    for (int t = 0; t < 6; t++) {
        int c = lane + 32*t;
        orow[c] = __float2bfloat16((v[t]-mu)*inv*gamma[c] + beta[c]);
    }
}

// ---------- shared MMA helpers ----------
__device__ __forceinline__ void ldsm4(uint32_t f[4], uint32_t addr) {
    asm volatile("ldmatrix.sync.aligned.m8n8.x4.shared.b16 {%0,%1,%2,%3}, [%4];"
        : "=r"(f[0]), "=r"(f[1]), "=r"(f[2]), "=r"(f[3]) : "r"(addr));
}
__device__ __forceinline__ void ldsm4t(uint32_t f[4], uint32_t addr) {
    asm volatile("ldmatrix.sync.aligned.m8n8.x4.trans.shared.b16 {%0,%1,%2,%3}, [%4];"
        : "=r"(f[0]), "=r"(f[1]), "=r"(f[2]), "=r"(f[3]) : "r"(addr));
}
__device__ __forceinline__ void mma_bf16(float c[4], const uint32_t a[4],
                                         uint32_t b0, uint32_t b1) {
    asm volatile("mma.sync.aligned.m16n8k16.row.col.f32.bf16.bf16.f32 "
        "{%0,%1,%2,%3}, {%4,%5,%6,%7}, {%8,%9}, {%0,%1,%2,%3};"
        : "+f"(c[0]), "+f"(c[1]), "+f"(c[2]), "+f"(c[3])
        : "r"(a[0]), "r"(a[1]), "r"(a[2]), "r"(a[3]), "r"(b0), "r"(b1));
}
__device__ __forceinline__ void cp16(uint32_t dst, const void* src) {
    asm volatile("cp.async.cg.shared.global [%0], [%1], 16;" :: "r"(dst), "l"(src));
}

// ============================================================
// BF16 tensor-core NT-GEMM with ldmatrix + cp.async 2-stage
// (verified R6-R9) — used for QKV (EPI 0) and MLP (EPI 2)
// ============================================================
__device__ __forceinline__ uint32_t swzoff(int r, int c8) {
    return (uint32_t)(r*32 + ((c8 ^ ((r>>1)&3)) << 3));
}

template<int EPI>
__global__ __launch_bounds__(256) void k_gemm_bf16(
        const __nv_bfloat16* __restrict__ A,
        const __nv_bfloat16* __restrict__ W,
        const float* __restrict__ bias,
        void* __restrict__ outv,
        const float* __restrict__ resid,
        int Ntot)
{
    __shared__ __align__(16) __nv_bfloat16 As[2][64*32];
    __shared__ __align__(16) __nv_bfloat16 Bs[2][192*32];
    int tid = threadIdx.x, lane = tid & 31, w = tid >> 5;
    int wm = (w & 1) * 32, wn = (w >> 1) * 48;
    int m0 = blockIdx.x * 64, n0 = blockIdx.y * 192;

    uint32_t sA = (uint32_t)__cvta_generic_to_shared(&As[0][0]);
    uint32_t sB = (uint32_t)__cvta_generic_to_shared(&Bs[0][0]);
    const uint32_t stgA = 64*32*2, stgB = 192*32*2;

    int arow = tid >> 2, aslot = tid & 3;
    const __nv_bfloat16* asrc = A + (size_t)(m0 + arow)*192 + aslot*8;
    uint32_t adst = sA + 2*swzoff(arow, aslot);
    const __nv_bfloat16* bsrc[3];
    uint32_t bdst[3];
#pragma unroll
    for (int p = 0; p < 3; p++) {
        int i = tid + p*256;
        int br = i >> 2, bs = i & 3;
        bsrc[p] = W + (size_t)(n0 + br)*192 + bs*8;
        bdst[p] = sB + 2*swzoff(br, bs);
    }

    float acc[2][6][4];
#pragma unroll
    for (int mt = 0; mt < 2; mt++)
#pragma unroll
        for (int nt = 0; nt < 6; nt++)
#pragma unroll
            for (int i = 0; i < 4; i++) acc[mt][nt][i] = 0.f;

    cp16(adst, asrc);
#pragma unroll
    for (int p = 0; p < 3; p++) cp16(bdst[p], bsrc[p]);
    asm volatile("cp.async.commit_group;");

    for (int it = 0; it < 6; it++) {
        asm volatile("cp.async.wait_group 0;");
        __syncthreads();
        if (it + 1 < 6) {
            int st = (it + 1) & 1;
            int koff = (it + 1) * 32;
            cp16(adst + st*stgA, asrc + koff);
#pragma unroll
            for (int p = 0; p < 3; p++) cp16(bdst[p] + st*stgB, bsrc[p] + koff);
            asm volatile("cp.async.commit_group;");
        }
        uint32_t baseA = sA + (it & 1)*stgA;
        uint32_t baseB = sB + (it & 1)*stgB;
#pragma unroll
        for (int kk8 = 0; kk8 < 4; kk8 += 2) {
            uint32_t af[2][4];
#pragma unroll
            for (int mh = 0; mh < 2; mh++) {
                int row = wm + mh*16 + (lane & 15);
                int c8  = kk8 + (lane >> 4);
                ldsm4(af[mh], baseA + 2*swzoff(row, c8));
            }
            uint32_t bfr[3][4];
#pragma unroll
            for (int nh = 0; nh < 3; nh++) {
                int row = wn + nh*16 + ((lane >> 4) << 3) + (lane & 7);
                int c8  = kk8 + ((lane >> 3) & 1);
                ldsm4(bfr[nh], baseB + 2*swzoff(row, c8));
            }
#pragma unroll
            for (int mt = 0; mt < 2; mt++)
#pragma unroll
                for (int nt = 0; nt < 6; nt++)
                    mma_bf16(acc[mt][nt], af[mt],
                             bfr[nt >> 1][(nt & 1)*2], bfr[nt >> 1][(nt & 1)*2 + 1]);
        }
        __syncthreads();
    }

    int r = lane >> 2, q2 = (lane & 3) * 2;
    float bb[6][2];
#pragma unroll
    for (int nt = 0; nt < 6; nt++) {
        bb[nt][0] = bias[n0 + wn + nt*8 + q2];
        bb[nt][1] = bias[n0 + wn + nt*8 + q2 + 1];
    }

#pragma unroll
    for (int mt = 0; mt < 2; mt++)
#pragma unroll
    for (int half = 0; half < 2; half++) {
        int m = m0 + wm + mt*16 + r + half*8;
        if (EPI == 0) {
            __nv_bfloat16* orow = (__nv_bfloat16*)outv + (size_t)m*Ntot + n0 + wn;
#pragma unroll
            for (int nt = 0; nt < 6; nt++) {
                float x0 = acc[mt][nt][half*2+0] + bb[nt][0];
                float x1 = acc[mt][nt][half*2+1] + bb[nt][1];
                *(__nv_bfloat162*)(orow + nt*8 + q2) = __floats2bfloat162_rn(x0, x1);
            }
        } else {
            float* orow = (float*)outv + (size_t)m*Cc + n0 + wn;
            const float* rrow = resid + (size_t)m*Cc + n0 + wn;
#pragma unroll
            for (int nt = 0; nt < 6; nt++) {
                float x0 = acc[mt][nt][half*2+0] + bb[nt][0];
                float x1 = acc[mt][nt][half*2+1] + bb[nt][1];
                x0 = 0.5f*x0*(1.f + erff(x0*0.70710678118654752f));
                x1 = 0.5f*x1*(1.f + erff(x1*0.70710678118654752f));
                x0 += rrow[nt*8 + q2];
                x1 += rrow[nt*8 + q2 + 1];
                *(float2*)(orow + nt*8 + q2) = make_float2(x0, x1);
            }
        }
    }
}

// ============================================================
// Kernel 3: fused MMA attention + proj + window-reverse scatter.
// Block = window (2048 blocks), 256 threads (8 warps).
// Heads in 3 pairs: warps 0-3 head 2i, warps 4-7 head 2i+1.
// O accumulated in smem (swizzled), then proj GEMM + scatter.
// ============================================================
// Os layout: row stride 192 bf16 (384B = 24 chunks); within each
// aligned 8-chunk group, chunk index is XORed with (r&7).
__device__ __forceinline__ uint32_t osOff(int r, int c8) {   // bf16 elems
    return (uint32_t)(r*192 + (((c8 & ~7) + ((c8 & 7) ^ (r & 7))) << 3));
}

__global__ __launch_bounds__(256) void k_attn_proj(
        const __nv_bfloat16* __restrict__ qkv,
        const float* __restrict__ tbl,
        const __nv_bfloat16* __restrict__ Wp,
        const float* __restrict__ proj_b,
        __nv_bfloat16* __restrict__ outp)
{
    int win = blockIdx.x;
    int tid = threadIdx.x, lane = tid & 31, w = tid >> 5;

    __shared__ __align__(16) __nv_bfloat16 QKa[2][64*64];
    __shared__ __align__(16) __nv_bfloat16 Va [2][64*32];
    __shared__ __align__(16) __nv_bfloat16 Os [64*192];
    __shared__ __align__(16) __nv_bfloat16 WpS[2][192*32];

    uint32_t sQK0 = (uint32_t)__cvta_generic_to_shared(&QKa[0][0]);
    uint32_t sV0  = (uint32_t)__cvta_generic_to_shared(&Va[0][0]);
    uint32_t sOs  = (uint32_t)__cvta_generic_to_shared(&Os[0]);
    uint32_t sWp  = (uint32_t)__cvta_generic_to_shared(&WpS[0][0]);
    const uint32_t stgW = 192*32*2;

    const __nv_bfloat16* base = qkv + (size_t)win*NN*576;

    // prefetch Wp stage 0 (overlaps the whole attention phase)
    {
        uint32_t bdst[3]; const __nv_bfloat16* bsrc[3];
#pragma unroll
        for (int p = 0; p < 3; p++) {
            int i = tid + p*256;
            int br = i >> 2, bs = i & 3;
            bsrc[p] = Wp + (size_t)br*192 + bs*8;
            bdst[p] = sWp + 2*swzoff(br, bs);
        }
#pragma unroll
        for (int p = 0; p < 3; p++) cp16(bdst[p], bsrc[p]);
        asm volatile("cp.async.commit_group;");
    }

    int nw = win & 63;
    int hb = w >> 2;        // which head of the pair this warp works on
    int wq = w & 3;         // warp quarter -> rows [wq*16, wq*16+16)

    for (int hp = 0; hp < 3; hp++) {
        // ---- load head-pair QK (packed) + V, zero-padded ----
        for (int idx = tid; idx < 1536; idx += 256) {
            int hbl = idx >= 768;
            int j = idx & 767;
            int h = 2*hp + hbl;
            if (j < 512) {
                int r = j >> 3, c8 = j & 7;
                float4 val = make_float4(0.f,0.f,0.f,0.f);
                if (r < NN) {
                    int gchunk = (c8 >= 4) ? (24 + h*4 + (c8 - 4)) : (h*4 + c8);
                    val = *(const float4*)(base + (size_t)r*576 + gchunk*8);
                }
                *(float4*)(&QKa[hbl][0] + r*64 + ((c8 ^ (r & 7)) << 3)) = val;
            } else {
                int jj = j - 512;
                int r = jj >> 2, c8 = jj & 3;
                float4 val = make_float4(0.f,0.f,0.f,0.f);
                if (r < NN)
                    val = *(const float4*)(base + (size_t)r*576 + (48 + h*4 + c8)*8);
                *(float4*)(&Va[hbl][0] + r*32 + ((c8 ^ (r & 3)) << 3)) = val;
            }
        }
        __syncthreads();

        int h = 2*hp + hb;
        uint32_t sQK = sQK0 + hb*(64*64*2);
        uint32_t sV  = sV0  + hb*(64*32*2);

        // ---- S = Q @ K^T : warp rows [16wq,16wq+16), cols 0..63 ----
        float sacc[8][4];
#pragma unroll
        for (int nt = 0; nt < 8; nt++)
#pragma unroll
            for (int i = 0; i < 4; i++) sacc[nt][i] = 0.f;

#pragma unroll
        for (int kk = 0; kk < 2; kk++) {
            uint32_t a[4];
            {
                int j = lane >> 3;
                int row = wq*16 + (j & 1)*8 + (lane & 7);
                int c8  = kk*2 + (j >> 1);
                ldsm4(a, sQK + 2*(row*64 + ((c8 ^ (row & 7)) << 3)));
            }
            uint32_t b[4][4];
#pragma unroll
            for (int t = 0; t < 4; t++) {
                int row = t*16 + ((lane >> 4) << 3) + (lane & 7);
                int c8  = 4 + kk*2 + ((lane >> 3) & 1);
                ldsm4(b[t], sQK + 2*(row*64 + ((c8 ^ (row & 7)) << 3)));
            }
#pragma unroll
            for (int nt = 0; nt < 8; nt++)
                mma_bf16(sacc[nt], a, b[nt >> 1][(nt & 1)*2], b[nt >> 1][(nt & 1)*2 + 1]);
        }

        // ---- softmax in registers (quad shfl reduce) ----
        int r = lane >> 2, q2 = (lane & 3)*2;
        int row0 = wq*16 + r;
        const float* t0 = tbl + (((size_t)h*64 + nw)*64 + row0)*64;
        const float* t1 = t0 + 8*64;

        float v0[16], v1[16];
        float mx0 = -1e30f, mx1 = -1e30f;
#pragma unroll
        for (int nt = 0; nt < 8; nt++) {
            float2 b0 = *(const float2*)(t0 + nt*8 + q2);
            float2 b1 = *(const float2*)(t1 + nt*8 + q2);
            v0[2*nt]   = fmaf(sacc[nt][0], QSCALE, b0.x);
            v0[2*nt+1] = fmaf(sacc[nt][1], QSCALE, b0.y);
            v1[2*nt]   = fmaf(sacc[nt][2], QSCALE, b1.x);
            v1[2*nt+1] = fmaf(sacc[nt][3], QSCALE, b1.y);
            mx0 = fmaxf(mx0, fmaxf(v0[2*nt], v0[2*nt+1]));
            mx1 = fmaxf(mx1, fmaxf(v1[2*nt], v1[2*nt+1]));
        }
        mx0 = fmaxf(mx0, __shfl_xor_sync(0xffffffffu, mx0, 1));
        mx0 = fmaxf(mx0, __shfl_xor_sync(0xffffffffu, mx0, 2));
        mx1 = fmaxf(mx1, __shfl_xor_sync(0xffffffffu, mx1, 1));
        mx1 = fmaxf(mx1, __shfl_xor_sync(0xffffffffu, mx1, 2));

        uint32_t pk0[8], pk1[8];
        float sum0 = 0.f, sum1 = 0.f;
#pragma unroll
        for (int nt = 0; nt < 8; nt++) {
            float e0a = __expf(v0[2*nt]   - mx0);
            float e0b = __expf(v0[2*nt+1] - mx0);
            float e1a = __expf(v1[2*nt]   - mx1);
            float e1b = __expf(v1[2*nt+1] - mx1);
            sum0 += e0a + e0b;
            sum1 += e1a + e1b;
            __nv_bfloat162 p0 = __floats2bfloat162_rn(e0a, e0b);
            __nv_bfloat162 p1 = __floats2bfloat162_rn(e1a, e1b);
            pk0[nt] = *(uint32_t*)&p0;
            pk1[nt] = *(uint32_t*)&p1;
        }
        sum0 += __shfl_xor_sync(0xffffffffu, sum0, 1);
        sum0 += __shfl_xor_sync(0xffffffffu, sum0, 2);
        sum1 += __shfl_xor_sync(0xffffffffu, sum1, 1);
        sum1 += __shfl_xor_sync(0xffffffffu, sum1, 2);
        float ri0 = 1.f / sum0, ri1 = 1.f / sum1;

        // ---- O = P @ V ----
        float oacc[4][4];
#pragma unroll
        for (int nt = 0; nt < 4; nt++)
#pragma unroll
            for (int i = 0; i < 4; i++) oacc[nt][i] = 0.f;

#pragma unroll
        for (int kk = 0; kk < 4; kk++) {
            uint32_t a[4] = { pk0[2*kk], pk1[2*kk], pk0[2*kk+1], pk1[2*kk+1] };
            uint32_t b[2][4];
#pragma unroll
            for (int t = 0; t < 2; t++) {
                int j = lane >> 3;
                int row = kk*16 + (j & 1)*8 + (lane & 7);
                int c8  = t*2 + (j >> 1);
                ldsm4t(b[t], sV + 2*(row*32 + ((c8 ^ (row & 3)) << 3)));
            }
#pragma unroll
            for (int nt = 0; nt < 4; nt++)
                mma_bf16(oacc[nt], a, b[nt >> 1][(nt & 1)*2], b[nt >> 1][(nt & 1)*2 + 1]);
        }

        // normalized O -> Os (smem, swizzled). Pad rows harmless.
#pragma unroll
        for (int nt = 0; nt < 4; nt++) {
            int cD = h*4 + nt;
            __nv_bfloat162 o0 = __floats2bfloat162_rn(oacc[nt][0]*ri0, oacc[nt][1]*ri0);
            __nv_bfloat162 o1 = __floats2bfloat162_rn(oacc[nt][2]*ri1, oacc[nt][3]*ri1);
            *(__nv_bfloat162*)(&Os[0] + osOff(row0,     cD) + q2) = o0;
            *(__nv_bfloat162*)(&Os[0] + osOff(row0 + 8, cD) + q2) = o1;
        }
        __syncthreads();   // Os/QKa reuse barrier
    }

    // ================= proj phase: Out = Os @ Wp^T + b, scatter =================
    int wm = (w & 1) * 32, wn = (w >> 1) * 48;

    uint32_t bdst[3]; const __nv_bfloat16* bsrc[3];
#pragma unroll
    for (int p = 0; p < 3; p++) {
        int i = tid + p*256;
        int br = i >> 2, bs = i & 3;
        bsrc[p] = Wp + (size_t)br*192 + bs*8;
        bdst[p] = sWp + 2*swzoff(br, bs);
    }

    float acc[2][6][4];
#pragma unroll
    for (int mt = 0; mt < 2; mt++)
#pragma unroll
        for (int nt = 0; nt < 6; nt++)
#pragma unroll
            for (int i = 0; i < 4; i++) acc[mt][nt][i] = 0.f;

    for (int it = 0; it < 6; it++) {
        asm volatile("cp.async.wait_group 0;");
        __syncthreads();
        if (it + 1 < 6) {
            int st = (it + 1) & 1;
            int koff = (it + 1) * 32;
#pragma unroll
            for (int p = 0; p < 3; p++) cp16(bdst[p] + st*stgW, bsrc[p] + koff);
            asm volatile("cp.async.commit_group;");
        }
        uint32_t baseB = sWp + (it & 1)*stgW;
#pragma unroll
        for (int kk8 = 0; kk8 < 4; kk8 += 2) {
            uint32_t af[2][4];
#pragma unroll
            for (int mh = 0; mh < 2; mh++) {
                int row = wm + mh*16 + (lane & 15);
                int c8  = it*4 + kk8 + (lane >> 4);
                ldsm4(af[mh], sOs + 2*osOff(row, c8));
            }
            uint32_t bfr[3][4];
#pragma unroll
            for (int nh = 0; nh < 3; nh++) {
                int row = wn + nh*16 + ((lane >> 4) << 3) + (lane & 7);
                int c8  = kk8 + ((lane >> 3) & 1);
                ldsm4(bfr[nh], baseB + 2*swzoff(row, c8));
            }
#pragma unroll
            for (int mt = 0; mt < 2; mt++)
#pragma unroll
                for (int nt = 0; nt < 6; nt++)
                    mma_bf16(acc[mt][nt], af[mt],
                             bfr[nt >> 1][(nt & 1)*2], bfr[nt >> 1][(nt & 1)*2 + 1]);
        }
        __syncthreads();
    }

    // epilogue: bias + window-reverse scatter (bf16)
    int r = lane >> 2, q2 = (lane & 3)*2;
    float bb[6][2];
#pragma unroll
    for (int nt = 0; nt < 6; nt++) {
        bb[nt][0] = proj_b[wn + nt*8 + q2];
        bb[nt][1] = proj_b[wn + nt*8 + q2 + 1];
    }
    int bI = win >> 6, wr = win & 63;
    int wh = wr >> 3, ww = wr & 7;

#pragma unroll
    for (int mt = 0; mt < 2; mt++)
#pragma unroll
    for (int half = 0; half < 2; half++) {
        int n = wm + mt*16 + r + half*8;
        if (n >= NN) continue;
        int hs = wh*WSz + n/WSz;
        int ws = ww*WSz + n%WSz;
        int dh = (hs + SHIFT) % Hdim;
        int dw = (ws + SHIFT) % Wdim;
        __nv_bfloat16* orow = outp + ((size_t)bI*(Hdim*Wdim) + dh*Wdim + dw)*Cc + wn;
#pragma unroll
        for (int nt = 0; nt < 6; nt++) {
            float x0 = acc[mt][nt][half*2+0] + bb[nt][0];
            float x1 = acc[mt][nt][half*2+1] + bb[nt][1];
            *(__nv_bfloat162*)(orow + nt*8 + q2) = __floats2bfloat162_rn(x0, x1);
        }
    }
}

// ============================================================
extern "C" void kernel_launch(void* const* d_in, const int* in_sizes, int n_in,
                              void* d_out, int out_size)
{
    const float* inputs = (const float*)d_in[0];
    const float* mask   = (const float*)d_in[1];
    const float* n1g    = (const float*)d_in[2];
    const float* n1b    = (const float*)d_in[3];
    const float* qkv_w  = (const float*)d_in[4];
    const float* qkv_b  = (const float*)d_in[5];
    const float* table  = (const float*)d_in[6];
    const int*   rpi    = (const int*)  d_in[7];
    const float* proj_w = (const float*)d_in[8];
    const float* proj_b = (const float*)d_in[9];
    const float* lin_w  = (const float*)d_in[10];
    const float* lin_b  = (const float*)d_in[11];
    float* out = (float*)d_out;

    __nv_bfloat16 *p_win, *p_qkv, *p_attn, *p_wq, *p_wp, *p_wl;
    float* p_tbl;
    cudaGetSymbolAddress((void**)&p_win,  g_win);
    cudaGetSymbolAddress((void**)&p_qkv,  g_qkv);
    cudaGetSymbolAddress((void**)&p_attn, g_attn);
    cudaGetSymbolAddress((void**)&p_wq,   g_wq);
    cudaGetSymbolAddress((void**)&p_wp,   g_wp);
    cudaGetSymbolAddress((void**)&p_wl,   g_wl);
    cudaGetSymbolAddress((void**)&p_tbl,  g_tbl);

    // 0. weight conversion + combined bias/mask table
    k_cvt<<<(6*64*64*64 + 255)/256, 256>>>(qkv_w, proj_w, lin_w, table, rpi, mask);

    // 1. LN + shift + partition (bf16 out)
    k_ln_part<<<(TOK*32 + 255)/256, 256>>>(inputs, n1g, n1b, p_win);

    // 2. QKV GEMM -> bf16
    {
        dim3 grid(TOK/64, 3);
        k_gemm_bf16<0><<<grid, 256>>>(p_win, p_wq, qkv_b, p_qkv, nullptr, 3*Cc);
    }
    // 3. fused attention + proj + window-reverse scatter
    k_attn_proj<<<BWIN, 256>>>(p_qkv, p_tbl, p_wp, proj_b, p_attn);

    // 4. MLP GEMM + exact gelu + residual -> fp32 out
    {
        dim3 grid(TOK/64, 1);
        k_gemm_bf16<2><<<grid, 256>>>(p_attn, p_wl, lin_b, out, inputs, Cc);
    }
}